// round 10
// baseline (speedup 1.0000x reference)
#include <cuda_runtime.h>
#include <cuda_bf16.h>
#include <cstdint>

#define NTOK 8192
#define DIMQ 256
#define CD   64
#define NK   16384

#define OUT_OFF_IDX  (NTOK*DIMQ)
#define OUT_OFF_LOSS (NTOK*DIMQ + NTOK)

// ---------------- filter geometry ----------------
#define TILE_M 128             // tokens per CTA (8 warps x 16)
#define TILE_N 128             // codes per staged tile
#define FSPL   2               // K splits (grid.y)
#define KRANGE (NK/FSPL)       // 8192
#define NCT    (KRANGE/TILE_N) // 64 code tiles per CTA
#define MARGIN 2e-4f
#define CAP    8               // candidates per (token, tig-quarter)

// filter smem
#define OFF_ZH  0                      // 128 x 128B (SW128)    = 16384
#define OFF_E   16384                  // 2 x 128 x 128B        = 32768
#define OFF_BKQ 49152                  // 2 x 128 floats        = 1024
#define SMEM_F  50176

// ---- k_zp smem ----
#define ZROW 1040
#define SMEM_ZP (64*ZROW*2)
// ---- k_out smem ----
#define WPROW 272
#define SMEM_KO (256*WPROW + 128*WPROW)

#define SWZ128(o) ((o) ^ (((o) >> 3) & 0x70))

// ---------------- scratch ----------------
__device__ float g_zp[NTOK*CD];
__device__ float g_A[NTOK];
__device__ float g_Bk[NK];
__device__ __nv_bfloat16 g_zph[NTOK*CD];
__device__ __nv_bfloat16 g_eh[NK*CD];
__device__ int   g_ckand[FSPL*NTOK*4*CAP];
__device__ int   g_ccnt[FSPL*NTOK*4];
__device__ int   g_idx[NTOK];
__device__ float g_part[NTOK];

__device__ __forceinline__ uint32_t smem_u32(const void* p){
    uint32_t a;
    asm("{ .reg .u64 t; cvta.to.shared.u64 t, %1; cvt.u32.u64 %0, t; }"
        : "=r"(a) : "l"(p));
    return a;
}
__device__ __forceinline__ void ldsm4(uint32_t& r0, uint32_t& r1,
                                      uint32_t& r2, uint32_t& r3, uint32_t addr){
    asm volatile("ldmatrix.sync.aligned.m8n8.x4.shared.b16 {%0,%1,%2,%3}, [%4];"
        : "=r"(r0), "=r"(r1), "=r"(r2), "=r"(r3) : "r"(addr));
}
__device__ __forceinline__ void mma16816(float* d, const uint32_t* a,
                                         uint32_t b0, uint32_t b1){
    asm volatile("mma.sync.aligned.m16n8k16.row.col.f32.bf16.bf16.f32 "
        "{%0,%1,%2,%3}, {%4,%5,%6,%7}, {%8,%9}, {%0,%1,%2,%3};"
        : "+f"(d[0]), "+f"(d[1]), "+f"(d[2]), "+f"(d[3])
        : "r"(a[0]), "r"(a[1]), "r"(a[2]), "r"(a[3]), "r"(b0), "r"(b1));
}

// ---------------------------------------------------------------------------
// Kernel 1: zp = z @ Wq^T + bq  (strictly-sequential ascending-d chain,
// bit-matching -- DO NOT reorder).  + A = ||zp||^2 (tree bit-matching) +
// bf16-hi copy of zp for the filter.
// ---------------------------------------------------------------------------
__global__ __launch_bounds__(256) void k_zp(const float* __restrict__ z,
                                            const float* __restrict__ Wq,
                                            const float* __restrict__ bq){
    extern __shared__ char sm[];
    char* wsm = sm;
    char* zsm = sm + 64*ZROW;
    int tid = threadIdx.x;
    int ts = tid >> 6, c = tid & 63;
    int t0 = blockIdx.x * 64;

    const float4* wq4 = (const float4*)Wq;
    const float4* z4  = (const float4*)z;
#pragma unroll
    for (int i=0;i<16;i++){
        int lin = tid + 256*i;
        int r = lin >> 6, q = lin & 63;
        *(float4*)(wsm + r*ZROW + q*16) = wq4[r*64 + q];
        *(float4*)(zsm + r*ZROW + q*16) = z4[(t0+r)*64 + q];
    }
    __syncthreads();

    float acc[16];
#pragma unroll
    for (int i=0;i<16;i++) acc[i] = 0.f;
#pragma unroll 4
    for (int k4=0;k4<64;k4++){
        float4 w = *(const float4*)(wsm + c*ZROW + k4*16);
#pragma unroll
        for (int i=0;i<16;i++){
            float4 zz = *(const float4*)(zsm + (ts*16+i)*ZROW + k4*16);
            acc[i] = fmaf(w.x, zz.x, acc[i]);
            acc[i] = fmaf(w.y, zz.y, acc[i]);
            acc[i] = fmaf(w.z, zz.z, acc[i]);
            acc[i] = fmaf(w.w, zz.w, acc[i]);
        }
    }
    float bqc = bq[c];
    float vv[16];
#pragma unroll
    for (int i=0;i<16;i++){
        float v = acc[i] + bqc;
        int gt = t0 + ts*16 + i;
        g_zp[gt*CD + c] = v;
        g_zph[gt*CD + c] = __float2bfloat16(v);
        vv[i] = v*v;
    }
    __syncthreads();
#pragma unroll
    for (int i=0;i<16;i++)
        *(float*)(zsm + (ts*16+i)*ZROW + c*4) = vv[i];
    __syncthreads();
    int l = tid & 31, w = tid >> 5;
#pragma unroll
    for (int tt=0;tt<8;tt++){
        int t = w*8 + tt;
        float s = *(float*)(zsm + t*ZROW + l*4) + *(float*)(zsm + t*ZROW + (l+32)*4);
        s += __shfl_down_sync(0xffffffffu, s, 16);
        s += __shfl_down_sync(0xffffffffu, s, 8);
        s += __shfl_down_sync(0xffffffffu, s, 4);
        s += __shfl_down_sync(0xffffffffu, s, 2);
        s += __shfl_down_sync(0xffffffffu, s, 1);
        if (l==0) g_A[t0+t] = s;
    }
}

// ---------------------------------------------------------------------------
// Kernel 2: B[k] = ||emb_k||^2 + bf16-hi copy of emb
// ---------------------------------------------------------------------------
__global__ void k_B(const float* __restrict__ emb){
    int k = blockIdx.x*blockDim.x + threadIdx.x;
    if (k >= NK) return;
    const float4* e4 = (const float4*)(emb + k*CD);
    __nv_bfloat162* eh2 = (__nv_bfloat162*)(g_eh + k*CD);
    float s0=0.f,s1=0.f,s2=0.f,s3=0.f;
#pragma unroll
    for (int i=0;i<16;i++){
        float4 e = e4[i];
        s0=fmaf(e.x,e.x,s0); s1=fmaf(e.y,e.y,s1);
        s2=fmaf(e.z,e.z,s2); s3=fmaf(e.w,e.w,s3);
        eh2[2*i]   = __nv_bfloat162(__float2bfloat16(e.x), __float2bfloat16(e.y));
        eh2[2*i+1] = __nv_bfloat162(__float2bfloat16(e.z), __float2bfloat16(e.w));
    }
    g_Bk[k] = (s0+s1)+(s2+s3);
}

__global__ void k_nop(){}

// ---------------------------------------------------------------------------
// Kernel 3: filter -- HMMA (mma.sync m16n8k16 bf16) over zp_hi x emb_hi.
// Grid (64 token-tiles, 2 K-splits).  Warp tile 16 tokens x 128 codes.
// m = 2*ab_hat - B; per-thread running max + margin candidates.
// Worst-case |m_hat - m| <= 4e-5 << MARGIN/2: reference winner provably
// lands in the candidate set (exact rescore picks it).
// ---------------------------------------------------------------------------
__global__ __launch_bounds__(256) void k_filter(){
    extern __shared__ char sm[];
    uint32_t sbase = smem_u32(sm);
    float (*Bk_s)[128] = (float (*)[128])(sm + OFF_BKQ);
    int tid = threadIdx.x;
    int wid = tid >> 5, lane = tid & 31;
    int g   = lane >> 2, tig = lane & 3;
    int t0 = blockIdx.x * TILE_M;
    int kbase0 = blockIdx.y * KRANGE;

    // ---- stage zp_hi tile [128 tok x 128B], SW128 ----
    const uint4* zh4 = (const uint4*)g_zph;
    const uint4* eh4 = (const uint4*)g_eh;
#pragma unroll
    for (int i=0;i<4;i++){
        int lin = tid + 256*i;              // 0..1023
        int r = lin >> 3, c8 = lin & 7;
        *(uint4*)(sm + OFF_ZH + SWZ128(r*128 + c8*16)) = zh4[(t0+r)*8 + c8];
    }
    // prefetch e tile 0 + Bk
    uint4 pf[4];
#pragma unroll
    for (int i=0;i<4;i++){
        int lin = tid + 256*i;
        int r = lin >> 3, c8 = lin & 7;
        pf[i] = eh4[(kbase0 + r)*8 + c8];
    }
    float bkpf = (tid < 128) ? g_Bk[kbase0 + tid] : 0.f;
    __syncthreads();
#pragma unroll
    for (int i=0;i<4;i++){
        int lin = tid + 256*i;
        int r = lin >> 3, c8 = lin & 7;
        *(uint4*)(sm + OFF_E + SWZ128(r*128 + c8*16)) = pf[i];
    }
    if (tid < 128) Bk_s[0][tid] = bkpf;

    // ---- A fragments: once per CTA (zh staged & synced below in loop) ----
    uint32_t afr[4][4];
    {
        int arow = wid*16 + (lane & 7) + ((lane >> 3) & 1)*8;
        int acolh = ((lane >> 4) & 1)*16;
#pragma unroll
        for (int ks=0;ks<4;ks++){
            uint32_t addr = sbase + OFF_ZH + SWZ128(arow*128 + ks*32 + acolh);
            ldsm4(afr[ks][0], afr[ks][1], afr[ks][2], afr[ks][3], addr);
        }
    }

    // candidate state: 2 tokens per thread (rows g and g+8 of warp tile)
    float rmax[2] = {-3.402823466e38f, -3.402823466e38f};
    float cm[2][CAP]; int ck[2][CAP];
    int cnt[2] = {0,0}, ovf = 0;

    int brow = (lane & 7) + ((lane >> 4) & 1)*8;
    int bcolh = ((lane >> 3) & 1)*16;
    int buf = 0;

    for (int it=0; it<NCT; it++){
        int kb = kbase0 + it*TILE_N;
        if (it+1 < NCT){
            int kbn = kb + TILE_N;
#pragma unroll
            for (int i=0;i<4;i++){
                int lin = tid + 256*i;
                int r = lin >> 3, c8 = lin & 7;
                pf[i] = eh4[(kbn + r)*8 + c8];
            }
            if (tid < 128) bkpf = g_Bk[kbn + tid];
        }
        __syncthreads();      // buf stores visible; prior reads of buf^1 done
        if (it+1 < NCT){
            char* eb = sm + OFF_E + (buf^1)*16384;
#pragma unroll
            for (int i=0;i<4;i++){
                int lin = tid + 256*i;
                int r = lin >> 3, c8 = lin & 7;
                *(uint4*)(eb + SWZ128(r*128 + c8*16)) = pf[i];
            }
            if (tid < 128) Bk_s[buf^1][tid] = bkpf;
        }

        // ---- MMA: 16 tokens x 128 codes ----
        float dacc[16][4];
#pragma unroll
        for (int nt=0;nt<16;nt++){
            dacc[nt][0]=0.f; dacc[nt][1]=0.f; dacc[nt][2]=0.f; dacc[nt][3]=0.f;
        }
        uint32_t ebase = sbase + OFF_E + buf*16384;
#pragma unroll
        for (int ks=0;ks<4;ks++){
#pragma unroll
            for (int p=0;p<8;p++){
                uint32_t b0,b1,b2,b3;
                uint32_t addr = ebase + SWZ128((p*16 + brow)*128 + ks*32 + bcolh);
                ldsm4(b0,b1,b2,b3, addr);
                mma16816(dacc[2*p],   afr[ks], b0, b1);
                mma16816(dacc[2*p+1], afr[ks], b2, b3);
            }
        }

        // ---- epilogue: m = 2*ab - Bk, candidates ----
#pragma unroll
        for (int nt=0;nt<16;nt++){
            float2 bk = *(const float2*)&Bk_s[buf][nt*8 + 2*tig];
            int k0 = kb + nt*8 + 2*tig;
            float mv[2][2] = {
                { fmaf(2.f, dacc[nt][0], -bk.x), fmaf(2.f, dacc[nt][1], -bk.y) },
                { fmaf(2.f, dacc[nt][2], -bk.x), fmaf(2.f, dacc[nt][3], -bk.y) } };
#pragma unroll
            for (int ti=0;ti<2;ti++){
#pragma unroll
                for (int c01=0;c01<2;c01++){
                    float m = mv[ti][c01];
                    if (m >= rmax[ti] - MARGIN){
                        if (cnt[ti] == CAP){
                            int nc = 0;
                            for (int q=0;q<CAP;q++)
                                if (cm[ti][q] >= rmax[ti] - MARGIN){
                                    cm[ti][nc]=cm[ti][q]; ck[ti][nc]=ck[ti][q]; nc++;
                                }
                            if (nc == CAP){ ovf = 1; nc = 0; }
                            cnt[ti] = nc;
                        }
                        cm[ti][cnt[ti]] = m; ck[ti][cnt[ti]] = k0 + c01; cnt[ti]++;
                    }
                    if (m > rmax[ti]) rmax[ti] = m;
                }
            }
        }
        buf ^= 1;
    }

    // ---- write candidate lists: slot = ((split*NTOK+t)*4 + tig) ----
#pragma unroll
    for (int ti=0;ti<2;ti++){
        int t = t0 + wid*16 + g + ti*8;
        int slot = (blockIdx.y*NTOK + t)*4 + tig;
        g_ccnt[slot] = cnt[ti] | (ovf << 16);
        for (int q=0;q<cnt[ti];q++) g_ckand[slot*CAP + q] = ck[ti][q];
    }
}

// ---------------------------------------------------------------------------
// Kernel 4: exact rescore (sequential ascending-c fp32 chain + reference
// score rounding -- bit-identical to the passing R8 argmin scoring).
// Warp per token; lexicographic (s,k) min == first-index tie-break.
// ---------------------------------------------------------------------------
__global__ __launch_bounds__(256) void k_rescore(const float* __restrict__ emb,
                                                 float* __restrict__ d_out,
                                                 int out_size){
    int wid = threadIdx.x >> 5, lane = threadIdx.x & 31;
    int t = blockIdx.x*8 + wid;
    float A = g_A[t];
    const float4* zp4 = (const float4*)(g_zp + t*CD);
    float bv = 3.402823466e38f; int bi = 0x7fffffff;

    // 8 lists: (split 0..1) x (tig 0..3); 4 lanes per list, 2 slots per lane
    int L = lane >> 2;                       // 0..7
    int split = L >> 2, tig = L & 3;
    int slot = (split*NTOK + t)*4 + tig;
    int craw = g_ccnt[slot];
    int ovf = __any_sync(0xffffffffu, (craw >> 16) & 1);
    int n = craw & 0xffff;

    if (!ovf){
#pragma unroll
        for (int h=0;h<2;h++){
            int q = (lane & 3) + 4*h;
            if (q < n){
                int k = g_ckand[slot*CAP + q];
                const float4* e4 = (const float4*)(emb + k*CD);
                float ab = 0.f;
#pragma unroll
                for (int c4=0;c4<16;c4++){
                    float4 zz = zp4[c4]; float4 e = e4[c4];
                    ab = fmaf(zz.x, e.x, ab);
                    ab = fmaf(zz.y, e.y, ab);
                    ab = fmaf(zz.z, e.z, ab);
                    ab = fmaf(zz.w, e.w, ab);
                }
                float s = (A + g_Bk[k]) - 2.0f*ab;
                if (s < bv || (s == bv && k < bi)){ bv = s; bi = k; }
            }
        }
    } else {
        for (int k=lane; k<NK; k+=32){
            const float4* e4 = (const float4*)(emb + k*CD);
            float ab = 0.f;
#pragma unroll
            for (int c4=0;c4<16;c4++){
                float4 zz = zp4[c4]; float4 e = e4[c4];
                ab = fmaf(zz.x, e.x, ab);
                ab = fmaf(zz.y, e.y, ab);
                ab = fmaf(zz.z, e.z, ab);
                ab = fmaf(zz.w, e.w, ab);
            }
            float s = (A + g_Bk[k]) - 2.0f*ab;
            if (s < bv || (s == bv && k < bi)){ bv = s; bi = k; }
        }
    }
#pragma unroll
    for (int o=16;o>0;o>>=1){
        float v  = __shfl_xor_sync(0xffffffffu, bv, o);
        int   i2 = __shfl_xor_sync(0xffffffffu, bi, o);
        if (v < bv || (v == bv && i2 < bi)){ bv = v; bi = i2; }
    }
    if (lane == 0){
        g_idx[t] = bi;
        if (out_size > OUT_OFF_IDX + t) d_out[OUT_OFF_IDX + t] = (float)bi;
    }
}

// ---------------------------------------------------------------------------
// Kernel 5: out = emb[idx] @ Wp^T + bp  + commit-loss partials (as R8)
// ---------------------------------------------------------------------------
__global__ __launch_bounds__(256) void k_out(const float* __restrict__ emb,
                                             const float* __restrict__ Wp,
                                             const float* __restrict__ bp,
                                             float* __restrict__ d_out){
    extern __shared__ char sm[];
    char* wsm = sm;
    char* esm = sm + 256*WPROW;
    int tid = threadIdx.x;
    int t0 = blockIdx.x * 128;

    const float4* wp4 = (const float4*)Wp;
    const float4* em4 = (const float4*)emb;
#pragma unroll
    for (int i=0;i<16;i++){
        int lin = tid + 256*i;
        int d = lin >> 4, c4 = lin & 15;
        *(float4*)(wsm + d*WPROW + c4*16) = wp4[d*16 + c4];
    }
#pragma unroll
    for (int i=0;i<8;i++){
        int lin = tid + 256*i;
        int t = lin >> 4, c4 = lin & 15;
        int idx = g_idx[t0+t];
        *(float4*)(esm + t*WPROW + c4*16) = em4[idx*16 + c4];
    }
    __syncthreads();

    if (tid < 128){
        int t = tid;
        const float4* zq = (const float4*)(g_zp + (t0+t)*CD);
        float s = 0.f;
#pragma unroll
        for (int c4=0;c4<16;c4++){
            float4 e = *(const float4*)(esm + t*WPROW + c4*16);
            float4 zz = zq[c4];
            float d0 = e.x - zz.x, d1 = e.y - zz.y;
            float d2 = e.z - zz.z, d3 = e.w - zz.w;
            s = fmaf(d0,d0,s); s = fmaf(d1,d1,s);
            s = fmaf(d2,d2,s); s = fmaf(d3,d3,s);
        }
        g_part[t0+t] = s;
    }

    float w[64];
#pragma unroll
    for (int c4=0;c4<16;c4++){
        float4 ww = *(const float4*)(wsm + tid*WPROW + c4*16);
        w[4*c4+0]=ww.x; w[4*c4+1]=ww.y; w[4*c4+2]=ww.z; w[4*c4+3]=ww.w;
    }
    float bpv = bp[tid];
    for (int t=0;t<128;t++){
        float a0=0.f,a1=0.f,a2=0.f,a3=0.f;
#pragma unroll
        for (int c4=0;c4<16;c4++){
            float4 e = *(const float4*)(esm + t*WPROW + c4*16);
            a0 = fmaf(w[4*c4+0], e.x, a0);
            a1 = fmaf(w[4*c4+1], e.y, a1);
            a2 = fmaf(w[4*c4+2], e.z, a2);
            a3 = fmaf(w[4*c4+3], e.w, a3);
        }
        d_out[(t0+t)*DIMQ + tid] = (a0+a1)+(a2+a3) + bpv;
    }
}

// ---------------------------------------------------------------------------
// Kernel 6: loss = m*(1+BETA)
// ---------------------------------------------------------------------------
__global__ void k_loss(float* __restrict__ d_out, int out_size){
    __shared__ float sh[256];
    int tid = threadIdx.x;
    float s = 0.f;
    for (int i=tid;i<NTOK;i+=256) s += g_part[i];
    sh[tid] = s;
    __syncthreads();
    for (int o=128;o>0;o>>=1){
        if (tid < o) sh[tid] += sh[tid+o];
        __syncthreads();
    }
    if (tid==0 && out_size > OUT_OFF_LOSS){
        float m = sh[0] / (float)(NTOK*CD);
        d_out[OUT_OFF_LOSS] = m + 0.25f*m;
    }
}

// ---------------------------------------------------------------------------
extern "C" void kernel_launch(void* const* d_in, const int* in_sizes, int n_in,
                              void* d_out, int out_size){
    const float* z   = (const float*)d_in[0];
    const float* Wq  = (const float*)d_in[1];
    const float* bq  = (const float*)d_in[2];
    const float* emb = (const float*)d_in[3];
    const float* Wp  = (const float*)d_in[4];
    const float* bp  = (const float*)d_in[5];
    float* out = (float*)d_out;
    (void)in_sizes; (void)n_in;

    static int attr_done = 0;
    if (!attr_done){
        cudaFuncSetAttribute(k_zp,     cudaFuncAttributeMaxDynamicSharedMemorySize, SMEM_ZP);
        cudaFuncSetAttribute(k_filter, cudaFuncAttributeMaxDynamicSharedMemorySize, SMEM_F);
        cudaFuncSetAttribute(k_out,    cudaFuncAttributeMaxDynamicSharedMemorySize, SMEM_KO);
        attr_done = 1;
    }

    k_zp<<<NTOK/64, 256, SMEM_ZP>>>(z, Wq, bq);        // 0
    k_B<<<NK/256, 256>>>(emb);                         // 1
    k_nop<<<1, 32>>>();                                // 2
    dim3 gf(NTOK/TILE_M, FSPL);
    k_filter<<<gf, 256, SMEM_F>>>();                   // 3 (profiled)
    k_rescore<<<NTOK/8, 256>>>(emb, out, out_size);    // 4
    k_out<<<NTOK/128, 256, SMEM_KO>>>(emb, Wp, bp, out);
    k_loss<<<1, 256>>>(out, out_size);
}

// round 11
// speedup vs baseline: 32.1655x; 32.1655x over previous
#include <cuda_runtime.h>
#include <cuda_bf16.h>
#include <cstdint>

#define NTOK 8192
#define DIMQ 256
#define CD   64
#define NK   16384

#define OUT_OFF_IDX  (NTOK*DIMQ)
#define OUT_OFF_LOSS (NTOK*DIMQ + NTOK)

// ---------------- filter geometry ----------------
#define TILE_M 128             // tokens per CTA (8 warps x 16)
#define TILE_N 128             // codes per staged tile
#define FSPL   4               // K splits (grid.y) -> 256 CTAs
#define KRANGE (NK/FSPL)       // 4096
#define NCT    (KRANGE/TILE_N) // 32 code tiles per CTA
#define MARGIN 2e-4f
#define LISTCAP (1<<20)

// filter smem
#define OFF_ZH  0                      // 128 x 128B (SW128)    = 16384
#define OFF_E   16384                  // 2 x 128 x 128B        = 32768
#define OFF_BKQ 49152                  // 2 x 128 floats        = 1024
#define SMEM_F  50176

// ---- k_zp smem ----
#define ZROW 1040
#define SMEM_ZP (64*ZROW*2)
// ---- k_out smem ----
#define WPROW 272
#define SMEM_KO (256*WPROW + 128*WPROW)

#define SWZ128(o) ((o) ^ (((o) >> 3) & 0x70))

// ---------------- scratch ----------------
__device__ float g_zp[NTOK*CD];
__device__ float g_A[NTOK];
__device__ float g_Bk[NK];
__device__ __nv_bfloat16 g_zph[NTOK*CD];
__device__ __nv_bfloat16 g_eh[NK*CD];
__device__ unsigned int g_tmax[NTOK];
__device__ unsigned long long g_best[NTOK];
__device__ int g_list[LISTCAP];
__device__ int g_cnt;
__device__ int g_flag;
__device__ int g_idx[NTOK];
__device__ float g_part[NTOK];

__device__ __forceinline__ uint32_t smem_u32(const void* p){
    uint32_t a;
    asm("{ .reg .u64 t; cvta.to.shared.u64 t, %1; cvt.u32.u64 %0, t; }"
        : "=r"(a) : "l"(p));
    return a;
}
__device__ __forceinline__ void ldsm4(uint32_t& r0, uint32_t& r1,
                                      uint32_t& r2, uint32_t& r3, uint32_t addr){
    asm volatile("ldmatrix.sync.aligned.m8n8.x4.shared.b16 {%0,%1,%2,%3}, [%4];"
        : "=r"(r0), "=r"(r1), "=r"(r2), "=r"(r3) : "r"(addr));
}
__device__ __forceinline__ void mma16816(float* d, const uint32_t* a,
                                         uint32_t b0, uint32_t b1){
    asm volatile("mma.sync.aligned.m16n8k16.row.col.f32.bf16.bf16.f32 "
        "{%0,%1,%2,%3}, {%4,%5,%6,%7}, {%8,%9}, {%0,%1,%2,%3};"
        : "+f"(d[0]), "+f"(d[1]), "+f"(d[2]), "+f"(d[3])
        : "r"(a[0]), "r"(a[1]), "r"(a[2]), "r"(a[3]), "r"(b0), "r"(b1));
}
// orderable float <-> uint (monotone): max/min via integer atomics
__device__ __forceinline__ unsigned int ford(float f){
    unsigned int b = __float_as_uint(f);
    return (b & 0x80000000u) ? ~b : (b | 0x80000000u);
}
__device__ __forceinline__ float funord(unsigned int u){
    unsigned int b = (u & 0x80000000u) ? (u & 0x7fffffffu) : ~u;
    return __uint_as_float(b);
}

// ---------------------------------------------------------------------------
// Kernel 1: zp = z @ Wq^T + bq (strictly-sequential ascending-d chain --
// bit-matching, DO NOT reorder) + A tree (bit-matching) + bf16-hi copy.
// ---------------------------------------------------------------------------
__global__ __launch_bounds__(256) void k_zp(const float* __restrict__ z,
                                            const float* __restrict__ Wq,
                                            const float* __restrict__ bq){
    extern __shared__ char sm[];
    char* wsm = sm;
    char* zsm = sm + 64*ZROW;
    int tid = threadIdx.x;
    int ts = tid >> 6, c = tid & 63;
    int t0 = blockIdx.x * 64;

    const float4* wq4 = (const float4*)Wq;
    const float4* z4  = (const float4*)z;
#pragma unroll
    for (int i=0;i<16;i++){
        int lin = tid + 256*i;
        int r = lin >> 6, q = lin & 63;
        *(float4*)(wsm + r*ZROW + q*16) = wq4[r*64 + q];
        *(float4*)(zsm + r*ZROW + q*16) = z4[(t0+r)*64 + q];
    }
    __syncthreads();

    float acc[16];
#pragma unroll
    for (int i=0;i<16;i++) acc[i] = 0.f;
#pragma unroll 4
    for (int k4=0;k4<64;k4++){
        float4 w = *(const float4*)(wsm + c*ZROW + k4*16);
#pragma unroll
        for (int i=0;i<16;i++){
            float4 zz = *(const float4*)(zsm + (ts*16+i)*ZROW + k4*16);
            acc[i] = fmaf(w.x, zz.x, acc[i]);
            acc[i] = fmaf(w.y, zz.y, acc[i]);
            acc[i] = fmaf(w.z, zz.z, acc[i]);
            acc[i] = fmaf(w.w, zz.w, acc[i]);
        }
    }
    float bqc = bq[c];
    float vv[16];
#pragma unroll
    for (int i=0;i<16;i++){
        float v = acc[i] + bqc;
        int gt = t0 + ts*16 + i;
        g_zp[gt*CD + c] = v;
        g_zph[gt*CD + c] = __float2bfloat16(v);
        vv[i] = v*v;
    }
    __syncthreads();
#pragma unroll
    for (int i=0;i<16;i++)
        *(float*)(zsm + (ts*16+i)*ZROW + c*4) = vv[i];
    __syncthreads();
    int l = tid & 31, w = tid >> 5;
#pragma unroll
    for (int tt=0;tt<8;tt++){
        int t = w*8 + tt;
        float s = *(float*)(zsm + t*ZROW + l*4) + *(float*)(zsm + t*ZROW + (l+32)*4);
        s += __shfl_down_sync(0xffffffffu, s, 16);
        s += __shfl_down_sync(0xffffffffu, s, 8);
        s += __shfl_down_sync(0xffffffffu, s, 4);
        s += __shfl_down_sync(0xffffffffu, s, 2);
        s += __shfl_down_sync(0xffffffffu, s, 1);
        if (l==0) g_A[t0+t] = s;
    }
}

// ---------------------------------------------------------------------------
// Kernel 2: B[k] = ||emb_k||^2 + bf16-hi copy + per-launch scratch inits
// ---------------------------------------------------------------------------
__global__ void k_B(const float* __restrict__ emb){
    int k = blockIdx.x*blockDim.x + threadIdx.x;
    if (k == 0){ g_cnt = 0; g_flag = 0; }
    if (k < NTOK){
        g_tmax[k] = 0u;                       // encodes -max float
        g_best[k] = 0xFFFFFFFFFFFFFFFFULL;
    }
    if (k >= NK) return;
    const float4* e4 = (const float4*)(emb + k*CD);
    __nv_bfloat162* eh2 = (__nv_bfloat162*)(g_eh + k*CD);
    float s0=0.f,s1=0.f,s2=0.f,s3=0.f;
#pragma unroll
    for (int i=0;i<16;i++){
        float4 e = e4[i];
        s0=fmaf(e.x,e.x,s0); s1=fmaf(e.y,e.y,s1);
        s2=fmaf(e.z,e.z,s2); s3=fmaf(e.w,e.w,s3);
        eh2[2*i]   = __nv_bfloat162(__float2bfloat16(e.x), __float2bfloat16(e.y));
        eh2[2*i+1] = __nv_bfloat162(__float2bfloat16(e.z), __float2bfloat16(e.w));
    }
    g_Bk[k] = (s0+s1)+(s2+s3);
}

// ---------------------------------------------------------------------------
// Kernel 3: filter (two passes, SAME MMA core -> bitwise-identical m-hat).
// pass 0: per-token global max of m-hat (branch-free) -> g_tmax (atomicMax)
// pass 1: append (t,k) with m-hat >= tmax - MARGIN to global list
// ---------------------------------------------------------------------------
__global__ __launch_bounds__(256, 2) void k_filter(int pass){
    extern __shared__ char sm[];
    uint32_t sbase = smem_u32(sm);
    float (*Bk_s)[128] = (float (*)[128])(sm + OFF_BKQ);
    int tid = threadIdx.x;
    int wid = tid >> 5, lane = tid & 31;
    int g   = lane >> 2, tig = lane & 3;
    int t0 = blockIdx.x * TILE_M;
    int kbase0 = blockIdx.y * KRANGE;
    int tA = t0 + wid*16 + g, tB = tA + 8;

    float thrA = 0.f, thrB = 0.f;
    if (pass){
        thrA = funord(g_tmax[tA]) - MARGIN;
        thrB = funord(g_tmax[tB]) - MARGIN;
    }

    // ---- stage zp_hi tile [128 tok x 128B], SW128 ----
    const uint4* zh4 = (const uint4*)g_zph;
    const uint4* eh4 = (const uint4*)g_eh;
#pragma unroll
    for (int i=0;i<4;i++){
        int lin = tid + 256*i;
        int r = lin >> 3, c8 = lin & 7;
        *(uint4*)(sm + OFF_ZH + SWZ128(r*128 + c8*16)) = zh4[(t0+r)*8 + c8];
    }
    // prefetch e tile 0 + Bk
    uint4 pf[4];
#pragma unroll
    for (int i=0;i<4;i++){
        int lin = tid + 256*i;
        int r = lin >> 3, c8 = lin & 7;
        pf[i] = eh4[(kbase0 + r)*8 + c8];
    }
    float bkpf = (tid < 128) ? g_Bk[kbase0 + tid] : 0.f;
    __syncthreads();
#pragma unroll
    for (int i=0;i<4;i++){
        int lin = tid + 256*i;
        int r = lin >> 3, c8 = lin & 7;
        *(uint4*)(sm + OFF_E + SWZ128(r*128 + c8*16)) = pf[i];
    }
    if (tid < 128) Bk_s[0][tid] = bkpf;

    // ---- A fragments once (zh synced by the loop-top __syncthreads) ----
    uint32_t afr[4][4];
    {
        int arow = wid*16 + (lane & 7) + ((lane >> 3) & 1)*8;
        int acolh = ((lane >> 4) & 1)*16;
#pragma unroll
        for (int ks=0;ks<4;ks++){
            uint32_t addr = sbase + OFF_ZH + SWZ128(arow*128 + ks*32 + acolh);
            ldsm4(afr[ks][0], afr[ks][1], afr[ks][2], afr[ks][3], addr);
        }
    }

    float rmaxA = -3.402823466e38f, rmaxB = -3.402823466e38f;
    int brow = (lane & 7) + ((lane >> 4) & 1)*8;
    int bcolh = ((lane >> 3) & 1)*16;
    int buf = 0;

    for (int it=0; it<NCT; it++){
        int kb = kbase0 + it*TILE_N;
        if (it+1 < NCT){
            int kbn = kb + TILE_N;
#pragma unroll
            for (int i=0;i<4;i++){
                int lin = tid + 256*i;
                int r = lin >> 3, c8 = lin & 7;
                pf[i] = eh4[(kbn + r)*8 + c8];
            }
            if (tid < 128) bkpf = g_Bk[kbn + tid];
        }
        __syncthreads();
        if (it+1 < NCT){
            char* eb = sm + OFF_E + (buf^1)*16384;
#pragma unroll
            for (int i=0;i<4;i++){
                int lin = tid + 256*i;
                int r = lin >> 3, c8 = lin & 7;
                *(uint4*)(eb + SWZ128(r*128 + c8*16)) = pf[i];
            }
            if (tid < 128) Bk_s[buf^1][tid] = bkpf;
        }

        // ---- MMA: 16 tokens x 128 codes (identical in both passes) ----
        float dacc[16][4];
#pragma unroll
        for (int nt=0;nt<16;nt++){
            dacc[nt][0]=0.f; dacc[nt][1]=0.f; dacc[nt][2]=0.f; dacc[nt][3]=0.f;
        }
        uint32_t ebase = sbase + OFF_E + buf*16384;
#pragma unroll
        for (int ks=0;ks<4;ks++){
#pragma unroll
            for (int p=0;p<8;p++){
                uint32_t b0,b1,b2,b3;
                uint32_t addr = ebase + SWZ128((p*16 + brow)*128 + ks*32 + bcolh);
                ldsm4(b0,b1,b2,b3, addr);
                mma16816(dacc[2*p],   afr[ks], b0, b1);
                mma16816(dacc[2*p+1], afr[ks], b2, b3);
            }
        }

        // ---- epilogue ----
        float mx0 = -3.402823466e38f, mx1 = -3.402823466e38f;
#pragma unroll
        for (int nt=0;nt<16;nt++){
            float2 bk = *(const float2*)&Bk_s[buf][nt*8 + 2*tig];
            mx0 = fmaxf(mx0, fmaxf(fmaf(2.f, dacc[nt][0], -bk.x),
                                   fmaf(2.f, dacc[nt][1], -bk.y)));
            mx1 = fmaxf(mx1, fmaxf(fmaf(2.f, dacc[nt][2], -bk.x),
                                   fmaf(2.f, dacc[nt][3], -bk.y)));
        }
        if (pass == 0){
            rmaxA = fmaxf(rmaxA, mx0);
            rmaxB = fmaxf(rmaxB, mx1);
        } else if (mx0 >= thrA || mx1 >= thrB){
            // rare path: re-derive values and append hits
            for (int nt=0;nt<16;nt++){
                float2 bk = *(const float2*)&Bk_s[buf][nt*8 + 2*tig];
                int k0 = kb + nt*8 + 2*tig;
                float m00 = fmaf(2.f, dacc[nt][0], -bk.x);
                float m01 = fmaf(2.f, dacc[nt][1], -bk.y);
                float m10 = fmaf(2.f, dacc[nt][2], -bk.x);
                float m11 = fmaf(2.f, dacc[nt][3], -bk.y);
                if (m00 >= thrA){
                    int p2 = atomicAdd(&g_cnt, 1);
                    if (p2 < LISTCAP) g_list[p2] = (tA<<14) | k0; else g_flag = 1;
                }
                if (m01 >= thrA){
                    int p2 = atomicAdd(&g_cnt, 1);
                    if (p2 < LISTCAP) g_list[p2] = (tA<<14) | (k0+1); else g_flag = 1;
                }
                if (m10 >= thrB){
                    int p2 = atomicAdd(&g_cnt, 1);
                    if (p2 < LISTCAP) g_list[p2] = (tB<<14) | k0; else g_flag = 1;
                }
                if (m11 >= thrB){
                    int p2 = atomicAdd(&g_cnt, 1);
                    if (p2 < LISTCAP) g_list[p2] = (tB<<14) | (k0+1); else g_flag = 1;
                }
            }
        }
        buf ^= 1;
    }

    if (pass == 0){
        float r = rmaxA;
        r = fmaxf(r, __shfl_xor_sync(0xffffffffu, r, 1));
        r = fmaxf(r, __shfl_xor_sync(0xffffffffu, r, 2));
        if (tig == 0) atomicMax(&g_tmax[tA], ford(r));
        r = rmaxB;
        r = fmaxf(r, __shfl_xor_sync(0xffffffffu, r, 1));
        r = fmaxf(r, __shfl_xor_sync(0xffffffffu, r, 2));
        if (tig == 0) atomicMax(&g_tmax[tB], ford(r));
    }
}

// ---------------------------------------------------------------------------
// Kernel 4: exact rescore of list entries.  One thread per entry, strictly
// sequential ascending-c fp32 chain + reference score rounding (bit-matches
// the passing R8 scoring).  u64 atomicMin(ford(s), k) == first-index tie-break.
// Flag set (cap overflow) -> exact full scan per token (correct, slow).
// ---------------------------------------------------------------------------
__global__ __launch_bounds__(256) void k_rescore(const float* __restrict__ emb){
    int gtid = blockIdx.x*blockDim.x + threadIdx.x;
    int nthr = gridDim.x*blockDim.x;
    if (!g_flag){
        int cnt = g_cnt; if (cnt > LISTCAP) cnt = LISTCAP;
        for (int i = gtid; i < cnt; i += nthr){
            int pk = g_list[i];
            int t = pk >> 14, k = pk & 16383;
            const float4* zp4 = (const float4*)(g_zp + t*CD);
            const float4* e4  = (const float4*)(emb + k*CD);
            float ab = 0.f;
#pragma unroll
            for (int c4=0;c4<16;c4++){
                float4 zz = zp4[c4]; float4 e = e4[c4];
                ab = fmaf(zz.x, e.x, ab);
                ab = fmaf(zz.y, e.y, ab);
                ab = fmaf(zz.z, e.z, ab);
                ab = fmaf(zz.w, e.w, ab);
            }
            float s = (g_A[t] + g_Bk[k]) - 2.0f*ab;
            unsigned long long u = ((unsigned long long)ford(s) << 32) | (unsigned)k;
            atomicMin(&g_best[t], u);
        }
    } else {
        int wid = gtid >> 5, lane = gtid & 31;
        int nw = nthr >> 5;
        for (int t = wid; t < NTOK; t += nw){
            const float4* zp4 = (const float4*)(g_zp + t*CD);
            float A = g_A[t];
            float bv = 3.402823466e38f; int bi = 0x7fffffff;
            for (int k=lane; k<NK; k+=32){
                const float4* e4 = (const float4*)(emb + k*CD);
                float ab = 0.f;
#pragma unroll
                for (int c4=0;c4<16;c4++){
                    float4 zz = zp4[c4]; float4 e = e4[c4];
                    ab = fmaf(zz.x, e.x, ab);
                    ab = fmaf(zz.y, e.y, ab);
                    ab = fmaf(zz.z, e.z, ab);
                    ab = fmaf(zz.w, e.w, ab);
                }
                float s = (A + g_Bk[k]) - 2.0f*ab;
                if (s < bv || (s == bv && k < bi)){ bv = s; bi = k; }
            }
            unsigned long long u = ((unsigned long long)ford(bv) << 32) | (unsigned)bi;
            atomicMin(&g_best[t], u);
        }
    }
}

// ---------------------------------------------------------------------------
// Kernel 4.5: finalize indices
// ---------------------------------------------------------------------------
__global__ void k_fin(float* __restrict__ d_out, int out_size){
    int t = blockIdx.x*blockDim.x + threadIdx.x;
    if (t >= NTOK) return;
    int bi = (int)(unsigned)(g_best[t] & 0xFFFFFFFFULL);
    g_idx[t] = bi;
    if (out_size > OUT_OFF_IDX + t) d_out[OUT_OFF_IDX + t] = (float)bi;
}

// ---------------------------------------------------------------------------
// Kernel 5: out = emb[idx] @ Wp^T + bp + commit-loss partials (as R8)
// ---------------------------------------------------------------------------
__global__ __launch_bounds__(256) void k_out(const float* __restrict__ emb,
                                             const float* __restrict__ Wp,
                                             const float* __restrict__ bp,
                                             float* __restrict__ d_out){
    extern __shared__ char sm[];
    char* wsm = sm;
    char* esm = sm + 256*WPROW;
    int tid = threadIdx.x;
    int t0 = blockIdx.x * 128;

    const float4* wp4 = (const float4*)Wp;
    const float4* em4 = (const float4*)emb;
#pragma unroll
    for (int i=0;i<16;i++){
        int lin = tid + 256*i;
        int d = lin >> 4, c4 = lin & 15;
        *(float4*)(wsm + d*WPROW + c4*16) = wp4[d*16 + c4];
    }
#pragma unroll
    for (int i=0;i<8;i++){
        int lin = tid + 256*i;
        int t = lin >> 4, c4 = lin & 15;
        int idx = g_idx[t0+t];
        *(float4*)(esm + t*WPROW + c4*16) = em4[idx*16 + c4];
    }
    __syncthreads();

    if (tid < 128){
        int t = tid;
        const float4* zq = (const float4*)(g_zp + (t0+t)*CD);
        float s = 0.f;
#pragma unroll
        for (int c4=0;c4<16;c4++){
            float4 e = *(const float4*)(esm + t*WPROW + c4*16);
            float4 zz = zq[c4];
            float d0 = e.x - zz.x, d1 = e.y - zz.y;
            float d2 = e.z - zz.z, d3 = e.w - zz.w;
            s = fmaf(d0,d0,s); s = fmaf(d1,d1,s);
            s = fmaf(d2,d2,s); s = fmaf(d3,d3,s);
        }
        g_part[t0+t] = s;
    }

    float w[64];
#pragma unroll
    for (int c4=0;c4<16;c4++){
        float4 ww = *(const float4*)(wsm + tid*WPROW + c4*16);
        w[4*c4+0]=ww.x; w[4*c4+1]=ww.y; w[4*c4+2]=ww.z; w[4*c4+3]=ww.w;
    }
    float bpv = bp[tid];
    for (int t=0;t<128;t++){
        float a0=0.f,a1=0.f,a2=0.f,a3=0.f;
#pragma unroll
        for (int c4=0;c4<16;c4++){
            float4 e = *(const float4*)(esm + t*WPROW + c4*16);
            a0 = fmaf(w[4*c4+0], e.x, a0);
            a1 = fmaf(w[4*c4+1], e.y, a1);
            a2 = fmaf(w[4*c4+2], e.z, a2);
            a3 = fmaf(w[4*c4+3], e.w, a3);
        }
        d_out[(t0+t)*DIMQ + tid] = (a0+a1)+(a2+a3) + bpv;
    }
}

// ---------------------------------------------------------------------------
// Kernel 6: loss = m*(1+BETA)
// ---------------------------------------------------------------------------
__global__ void k_loss(float* __restrict__ d_out, int out_size){
    __shared__ float sh[256];
    int tid = threadIdx.x;
    float s = 0.f;
    for (int i=tid;i<NTOK;i+=256) s += g_part[i];
    sh[tid] = s;
    __syncthreads();
    for (int o=128;o>0;o>>=1){
        if (tid < o) sh[tid] += sh[tid+o];
        __syncthreads();
    }
    if (tid==0 && out_size > OUT_OFF_LOSS){
        float m = sh[0] / (float)(NTOK*CD);
        d_out[OUT_OFF_LOSS] = m + 0.25f*m;
    }
}

// ---------------------------------------------------------------------------
extern "C" void kernel_launch(void* const* d_in, const int* in_sizes, int n_in,
                              void* d_out, int out_size){
    const float* z   = (const float*)d_in[0];
    const float* Wq  = (const float*)d_in[1];
    const float* bq  = (const float*)d_in[2];
    const float* emb = (const float*)d_in[3];
    const float* Wp  = (const float*)d_in[4];
    const float* bp  = (const float*)d_in[5];
    float* out = (float*)d_out;
    (void)in_sizes; (void)n_in;

    static int attr_done = 0;
    if (!attr_done){
        cudaFuncSetAttribute(k_zp,     cudaFuncAttributeMaxDynamicSharedMemorySize, SMEM_ZP);
        cudaFuncSetAttribute(k_filter, cudaFuncAttributeMaxDynamicSharedMemorySize, SMEM_F);
        cudaFuncSetAttribute(k_out,    cudaFuncAttributeMaxDynamicSharedMemorySize, SMEM_KO);
        attr_done = 1;
    }

    dim3 gf(NTOK/TILE_M, FSPL);                        // 64 x 4 = 256 CTAs
    k_zp<<<NTOK/64, 256, SMEM_ZP>>>(z, Wq, bq);        // 0
    k_B<<<NK/256, 256>>>(emb);                         // 1 (+ inits)
    k_filter<<<gf, 256, SMEM_F>>>(0);                  // 2: pass A (tmax)
    k_filter<<<gf, 256, SMEM_F>>>(1);                  // 3: pass B (candidates)
    k_rescore<<<256, 256>>>(emb);                      // 4
    k_fin<<<NTOK/256, 256>>>(out, out_size);           // 5
    k_out<<<NTOK/128, 256, SMEM_KO>>>(emb, Wp, bp, out);
    k_loss<<<1, 256>>>(out, out_size);
}

// round 12
// speedup vs baseline: 33.0383x; 1.0271x over previous
#include <cuda_runtime.h>
#include <cuda_bf16.h>
#include <cstdint>

#define NTOK 8192
#define DIMQ 256
#define CD   64
#define NK   16384

#define OUT_OFF_IDX  (NTOK*DIMQ)
#define OUT_OFF_LOSS (NTOK*DIMQ + NTOK)

// ---------------- filter geometry ----------------
#define TILE_M 128             // tokens per CTA (8 warps x 16)
#define TILE_N 128             // codes per staged tile
#define FSPL   4               // K splits (grid.y) -> 256 CTAs
#define KRANGE (NK/FSPL)       // 4096
#define NCT    (KRANGE/TILE_N) // 32 code tiles per CTA
#define NGRP   (NK/32)         // 512 code-groups of 32
#define MARGIN 2e-4f
#define LISTCAP (1<<20)

// filter smem
#define OFF_ZH  0                      // 128 x 128B (SW128)    = 16384
#define OFF_E   16384                  // 2 x 128 x 128B        = 32768
#define OFF_BKQ 49152                  // 2 x 128 floats        = 1024
#define SMEM_F  50176

// ---- k_zp smem ----
#define ZROW 1040
#define SMEM_ZP (64*ZROW*2)
// ---- k_out smem ----
#define WPROW 272
#define SMEM_KO (256*WPROW + 128*WPROW)

#define SWZ128(o) ((o) ^ (((o) >> 3) & 0x70))

// ---------------- scratch ----------------
__device__ float g_zp[NTOK*CD];
__device__ float g_A[NTOK];
__device__ float g_Bk[NK];
__device__ __nv_bfloat16 g_zph[NTOK*CD];
__device__ __nv_bfloat16 g_eh[NK*CD];
__device__ float g_gmax[NTOK*NGRP];       // per-(token, 32-code group) max of m-hat
__device__ unsigned long long g_best[NTOK];
__device__ int g_list[LISTCAP];
__device__ int g_cnt;
__device__ int g_flag;
__device__ int g_idx[NTOK];
__device__ float g_part[NTOK];

__device__ __forceinline__ uint32_t smem_u32(const void* p){
    uint32_t a;
    asm("{ .reg .u64 t; cvta.to.shared.u64 t, %1; cvt.u32.u64 %0, t; }"
        : "=r"(a) : "l"(p));
    return a;
}
__device__ __forceinline__ void ldsm4(uint32_t& r0, uint32_t& r1,
                                      uint32_t& r2, uint32_t& r3, uint32_t addr){
    asm volatile("ldmatrix.sync.aligned.m8n8.x4.shared.b16 {%0,%1,%2,%3}, [%4];"
        : "=r"(r0), "=r"(r1), "=r"(r2), "=r"(r3) : "r"(addr));
}
__device__ __forceinline__ void mma16816(float* d, const uint32_t* a,
                                         uint32_t b0, uint32_t b1){
    asm volatile("mma.sync.aligned.m16n8k16.row.col.f32.bf16.bf16.f32 "
        "{%0,%1,%2,%3}, {%4,%5,%6,%7}, {%8,%9}, {%0,%1,%2,%3};"
        : "+f"(d[0]), "+f"(d[1]), "+f"(d[2]), "+f"(d[3])
        : "r"(a[0]), "r"(a[1]), "r"(a[2]), "r"(a[3]), "r"(b0), "r"(b1));
}
// orderable float <-> uint (monotone)
__device__ __forceinline__ unsigned int ford(float f){
    unsigned int b = __float_as_uint(f);
    return (b & 0x80000000u) ? ~b : (b | 0x80000000u);
}

// ---------------------------------------------------------------------------
// Kernel 1: zp = z @ Wq^T + bq (strictly-sequential ascending-d chain --
// bit-matching, DO NOT reorder) + A tree (bit-matching) + bf16-hi copy.
// ---------------------------------------------------------------------------
__global__ __launch_bounds__(256) void k_zp(const float* __restrict__ z,
                                            const float* __restrict__ Wq,
                                            const float* __restrict__ bq){
    extern __shared__ char sm[];
    char* wsm = sm;
    char* zsm = sm + 64*ZROW;
    int tid = threadIdx.x;
    int ts = tid >> 6, c = tid & 63;
    int t0 = blockIdx.x * 64;

    const float4* wq4 = (const float4*)Wq;
    const float4* z4  = (const float4*)z;
#pragma unroll
    for (int i=0;i<16;i++){
        int lin = tid + 256*i;
        int r = lin >> 6, q = lin & 63;
        *(float4*)(wsm + r*ZROW + q*16) = wq4[r*64 + q];
        *(float4*)(zsm + r*ZROW + q*16) = z4[(t0+r)*64 + q];
    }
    __syncthreads();

    float acc[16];
#pragma unroll
    for (int i=0;i<16;i++) acc[i] = 0.f;
#pragma unroll 4
    for (int k4=0;k4<64;k4++){
        float4 w = *(const float4*)(wsm + c*ZROW + k4*16);
#pragma unroll
        for (int i=0;i<16;i++){
            float4 zz = *(const float4*)(zsm + (ts*16+i)*ZROW + k4*16);
            acc[i] = fmaf(w.x, zz.x, acc[i]);
            acc[i] = fmaf(w.y, zz.y, acc[i]);
            acc[i] = fmaf(w.z, zz.z, acc[i]);
            acc[i] = fmaf(w.w, zz.w, acc[i]);
        }
    }
    float bqc = bq[c];
    float vv[16];
#pragma unroll
    for (int i=0;i<16;i++){
        float v = acc[i] + bqc;
        int gt = t0 + ts*16 + i;
        g_zp[gt*CD + c] = v;
        g_zph[gt*CD + c] = __float2bfloat16(v);
        vv[i] = v*v;
    }
    __syncthreads();
#pragma unroll
    for (int i=0;i<16;i++)
        *(float*)(zsm + (ts*16+i)*ZROW + c*4) = vv[i];
    __syncthreads();
    int l = tid & 31, w = tid >> 5;
#pragma unroll
    for (int tt=0;tt<8;tt++){
        int t = w*8 + tt;
        float s = *(float*)(zsm + t*ZROW + l*4) + *(float*)(zsm + t*ZROW + (l+32)*4);
        s += __shfl_down_sync(0xffffffffu, s, 16);
        s += __shfl_down_sync(0xffffffffu, s, 8);
        s += __shfl_down_sync(0xffffffffu, s, 4);
        s += __shfl_down_sync(0xffffffffu, s, 2);
        s += __shfl_down_sync(0xffffffffu, s, 1);
        if (l==0) g_A[t0+t] = s;
    }
}

// ---------------------------------------------------------------------------
// Kernel 2: B[k] = ||emb_k||^2 + bf16-hi copy + per-launch scratch inits
// ---------------------------------------------------------------------------
__global__ void k_B(const float* __restrict__ emb){
    int k = blockIdx.x*blockDim.x + threadIdx.x;
    if (k == 0){ g_cnt = 0; g_flag = 0; }
    if (k < NTOK) g_best[k] = 0xFFFFFFFFFFFFFFFFULL;
    if (k >= NK) return;
    const float4* e4 = (const float4*)(emb + k*CD);
    __nv_bfloat162* eh2 = (__nv_bfloat162*)(g_eh + k*CD);
    float s0=0.f,s1=0.f,s2=0.f,s3=0.f;
#pragma unroll
    for (int i=0;i<16;i++){
        float4 e = e4[i];
        s0=fmaf(e.x,e.x,s0); s1=fmaf(e.y,e.y,s1);
        s2=fmaf(e.z,e.z,s2); s3=fmaf(e.w,e.w,s3);
        eh2[2*i]   = __nv_bfloat162(__float2bfloat16(e.x), __float2bfloat16(e.y));
        eh2[2*i+1] = __nv_bfloat162(__float2bfloat16(e.z), __float2bfloat16(e.w));
    }
    g_Bk[k] = (s0+s1)+(s2+s3);
}

__global__ void k_nop(){}

// ---------------------------------------------------------------------------
// Kernel 3: filter -- SINGLE pass.  HMMA bf16 m-hat = 2*ab - B; writes
// per-(token, 32-code-group) max to g_gmax.  Branch-free epilogue.
// ---------------------------------------------------------------------------
__global__ __launch_bounds__(256, 2) void k_filter(){
    extern __shared__ char sm[];
    uint32_t sbase = smem_u32(sm);
    float (*Bk_s)[128] = (float (*)[128])(sm + OFF_BKQ);
    int tid = threadIdx.x;
    int wid = tid >> 5, lane = tid & 31;
    int g   = lane >> 2, tig = lane & 3;
    int t0 = blockIdx.x * TILE_M;
    int kbase0 = blockIdx.y * KRANGE;
    int tA = t0 + wid*16 + g, tB = tA + 8;

    // ---- stage zp_hi tile [128 tok x 128B], SW128 ----
    const uint4* zh4 = (const uint4*)g_zph;
    const uint4* eh4 = (const uint4*)g_eh;
#pragma unroll
    for (int i=0;i<4;i++){
        int lin = tid + 256*i;
        int r = lin >> 3, c8 = lin & 7;
        *(uint4*)(sm + OFF_ZH + SWZ128(r*128 + c8*16)) = zh4[(t0+r)*8 + c8];
    }
    // prefetch e tile 0 + Bk
    uint4 pf[4];
#pragma unroll
    for (int i=0;i<4;i++){
        int lin = tid + 256*i;
        int r = lin >> 3, c8 = lin & 7;
        pf[i] = eh4[(kbase0 + r)*8 + c8];
    }
    float bkpf = (tid < 128) ? g_Bk[kbase0 + tid] : 0.f;
    __syncthreads();
#pragma unroll
    for (int i=0;i<4;i++){
        int lin = tid + 256*i;
        int r = lin >> 3, c8 = lin & 7;
        *(uint4*)(sm + OFF_E + SWZ128(r*128 + c8*16)) = pf[i];
    }
    if (tid < 128) Bk_s[0][tid] = bkpf;

    // ---- A fragments once ----
    uint32_t afr[4][4];
    {
        int arow = wid*16 + (lane & 7) + ((lane >> 3) & 1)*8;
        int acolh = ((lane >> 4) & 1)*16;
#pragma unroll
        for (int ks=0;ks<4;ks++){
            uint32_t addr = sbase + OFF_ZH + SWZ128(arow*128 + ks*32 + acolh);
            ldsm4(afr[ks][0], afr[ks][1], afr[ks][2], afr[ks][3], addr);
        }
    }

    int brow = (lane & 7) + ((lane >> 4) & 1)*8;
    int bcolh = ((lane >> 3) & 1)*16;
    int buf = 0;

    for (int it=0; it<NCT; it++){
        if (it+1 < NCT){
            int kbn = kbase0 + (it+1)*TILE_N;
#pragma unroll
            for (int i=0;i<4;i++){
                int lin = tid + 256*i;
                int r = lin >> 3, c8 = lin & 7;
                pf[i] = eh4[(kbn + r)*8 + c8];
            }
            if (tid < 128) bkpf = g_Bk[kbn + tid];
        }
        __syncthreads();
        if (it+1 < NCT){
            char* eb = sm + OFF_E + (buf^1)*16384;
#pragma unroll
            for (int i=0;i<4;i++){
                int lin = tid + 256*i;
                int r = lin >> 3, c8 = lin & 7;
                *(uint4*)(eb + SWZ128(r*128 + c8*16)) = pf[i];
            }
            if (tid < 128) Bk_s[buf^1][tid] = bkpf;
        }

        // ---- MMA: 16 tokens x 128 codes ----
        float dacc[16][4];
#pragma unroll
        for (int nt=0;nt<16;nt++){
            dacc[nt][0]=0.f; dacc[nt][1]=0.f; dacc[nt][2]=0.f; dacc[nt][3]=0.f;
        }
        uint32_t ebase = sbase + OFF_E + buf*16384;
#pragma unroll
        for (int ks=0;ks<4;ks++){
#pragma unroll
            for (int p=0;p<8;p++){
                uint32_t b0,b1,b2,b3;
                uint32_t addr = ebase + SWZ128((p*16 + brow)*128 + ks*32 + bcolh);
                ldsm4(b0,b1,b2,b3, addr);
                mma16816(dacc[2*p],   afr[ks], b0, b1);
                mma16816(dacc[2*p+1], afr[ks], b2, b3);
            }
        }

        // ---- epilogue: per-32-code-group maxes (branch-free) ----
        float gmA[4], gmB[4];
#pragma unroll
        for (int g32=0; g32<4; g32++){
            float a0 = -3.402823466e38f, b0 = -3.402823466e38f;
#pragma unroll
            for (int q=0;q<4;q++){
                int nt = g32*4 + q;
                float2 bk = *(const float2*)&Bk_s[buf][nt*8 + 2*tig];
                a0 = fmaxf(a0, fmaxf(fmaf(2.f, dacc[nt][0], -bk.x),
                                     fmaf(2.f, dacc[nt][1], -bk.y)));
                b0 = fmaxf(b0, fmaxf(fmaf(2.f, dacc[nt][2], -bk.x),
                                     fmaf(2.f, dacc[nt][3], -bk.y)));
            }
            // reduce across the 4 tig lanes (same token)
            a0 = fmaxf(a0, __shfl_xor_sync(0xffffffffu, a0, 1));
            a0 = fmaxf(a0, __shfl_xor_sync(0xffffffffu, a0, 2));
            b0 = fmaxf(b0, __shfl_xor_sync(0xffffffffu, b0, 1));
            b0 = fmaxf(b0, __shfl_xor_sync(0xffffffffu, b0, 2));
            gmA[g32] = a0; gmB[g32] = b0;
        }
        if (tig == 0){
            int gidx = blockIdx.y*(NCT*4) + it*4;
#pragma unroll
            for (int g32=0; g32<4; g32++){
                g_gmax[tA*NGRP + gidx + g32] = gmA[g32];
                g_gmax[tB*NGRP + gidx + g32] = gmB[g32];
            }
        }
        buf ^= 1;
    }
}

// ---------------------------------------------------------------------------
// Kernel 4: select -- per-token scan of 512 group maxes; append qualifying
// groups (>= M - MARGIN) to global list.  Warp per token.
// ---------------------------------------------------------------------------
__global__ __launch_bounds__(256) void k_select(){
    int wid = threadIdx.x >> 5, lane = threadIdx.x & 31;
    int t = blockIdx.x*8 + wid;
    const float4* gm4 = (const float4*)(g_gmax + t*NGRP);
    float4 v[4];
    float mx = -3.402823466e38f;
#pragma unroll
    for (int i=0;i<4;i++){
        v[i] = gm4[lane + 32*i];
        mx = fmaxf(mx, fmaxf(fmaxf(v[i].x, v[i].y), fmaxf(v[i].z, v[i].w)));
    }
#pragma unroll
    for (int o=16;o>0;o>>=1)
        mx = fmaxf(mx, __shfl_xor_sync(0xffffffffu, mx, o));
    float thr = mx - MARGIN;
#pragma unroll
    for (int i=0;i<4;i++){
        int gb = (lane + 32*i)*4;
        float c[4] = {v[i].x, v[i].y, v[i].z, v[i].w};
#pragma unroll
        for (int j=0;j<4;j++){
            if (c[j] >= thr){
                int p = atomicAdd(&g_cnt, 1);
                if (p < LISTCAP) g_list[p] = (t << 9) | (gb + j);
                else g_flag = 1;
            }
        }
    }
}

// ---------------------------------------------------------------------------
// Kernel 5: exact rescore.  Warp per list entry; lane per code in group.
// Strictly-sequential ascending-c fp32 chain + reference score rounding
// (bit-matches the passing scoring).  u64 atomicMin == first-index tie-break.
// ---------------------------------------------------------------------------
__global__ __launch_bounds__(256) void k_rescore(const float* __restrict__ emb){
    int gw = (blockIdx.x*blockDim.x + threadIdx.x) >> 5;
    int lane = threadIdx.x & 31;
    int nw = (gridDim.x*blockDim.x) >> 5;
    if (!g_flag){
        int cnt = g_cnt; if (cnt > LISTCAP) cnt = LISTCAP;
        for (int i = gw; i < cnt; i += nw){
            int pk = g_list[i];
            int t = pk >> 9, grp = pk & 511;
            int k = grp*32 + lane;
            const float4* zp4 = (const float4*)(g_zp + t*CD);
            const float4* e4  = (const float4*)(emb + k*CD);
            float ab = 0.f;
#pragma unroll
            for (int c4=0;c4<16;c4++){
                float4 zz = zp4[c4]; float4 e = e4[c4];
                ab = fmaf(zz.x, e.x, ab);
                ab = fmaf(zz.y, e.y, ab);
                ab = fmaf(zz.z, e.z, ab);
                ab = fmaf(zz.w, e.w, ab);
            }
            float s = (g_A[t] + g_Bk[k]) - 2.0f*ab;
            unsigned long long u = ((unsigned long long)ford(s) << 32) | (unsigned)k;
#pragma unroll
            for (int o=16;o>0;o>>=1)
                u = min(u, __shfl_xor_sync(0xffffffffu, u, o));
            if (lane == 0) atomicMin(&g_best[t], u);
        }
    } else {
        for (int t = gw; t < NTOK; t += nw){
            const float4* zp4 = (const float4*)(g_zp + t*CD);
            float A = g_A[t];
            float bv = 3.402823466e38f; int bi = 0x7fffffff;
            for (int k=lane; k<NK; k+=32){
                const float4* e4 = (const float4*)(emb + k*CD);
                float ab = 0.f;
#pragma unroll
                for (int c4=0;c4<16;c4++){
                    float4 zz = zp4[c4]; float4 e = e4[c4];
                    ab = fmaf(zz.x, e.x, ab);
                    ab = fmaf(zz.y, e.y, ab);
                    ab = fmaf(zz.z, e.z, ab);
                    ab = fmaf(zz.w, e.w, ab);
                }
                float s = (A + g_Bk[k]) - 2.0f*ab;
                if (s < bv || (s == bv && k < bi)){ bv = s; bi = k; }
            }
            unsigned long long u = ((unsigned long long)ford(bv) << 32) | (unsigned)bi;
#pragma unroll
            for (int o=16;o>0;o>>=1)
                u = min(u, __shfl_xor_sync(0xffffffffu, u, o));
            if (lane == 0) atomicMin(&g_best[t], u);
        }
    }
}

// ---------------------------------------------------------------------------
// Kernel 5.5: finalize indices
// ---------------------------------------------------------------------------
__global__ void k_fin(float* __restrict__ d_out, int out_size){
    int t = blockIdx.x*blockDim.x + threadIdx.x;
    if (t >= NTOK) return;
    int bi = (int)(unsigned)(g_best[t] & 0xFFFFFFFFULL);
    g_idx[t] = bi;
    if (out_size > OUT_OFF_IDX + t) d_out[OUT_OFF_IDX + t] = (float)bi;
}

// ---------------------------------------------------------------------------
// Kernel 6: out = emb[idx] @ Wp^T + bp + commit-loss partials
// ---------------------------------------------------------------------------
__global__ __launch_bounds__(256) void k_out(const float* __restrict__ emb,
                                             const float* __restrict__ Wp,
                                             const float* __restrict__ bp,
                                             float* __restrict__ d_out){
    extern __shared__ char sm[];
    char* wsm = sm;
    char* esm = sm + 256*WPROW;
    int tid = threadIdx.x;
    int t0 = blockIdx.x * 128;

    const float4* wp4 = (const float4*)Wp;
    const float4* em4 = (const float4*)emb;
#pragma unroll
    for (int i=0;i<16;i++){
        int lin = tid + 256*i;
        int d = lin >> 4, c4 = lin & 15;
        *(float4*)(wsm + d*WPROW + c4*16) = wp4[d*16 + c4];
    }
#pragma unroll
    for (int i=0;i<8;i++){
        int lin = tid + 256*i;
        int t = lin >> 4, c4 = lin & 15;
        int idx = g_idx[t0+t];
        *(float4*)(esm + t*WPROW + c4*16) = em4[idx*16 + c4];
    }
    __syncthreads();

    if (tid < 128){
        int t = tid;
        const float4* zq = (const float4*)(g_zp + (t0+t)*CD);
        float s = 0.f;
#pragma unroll
        for (int c4=0;c4<16;c4++){
            float4 e = *(const float4*)(esm + t*WPROW + c4*16);
            float4 zz = zq[c4];
            float d0 = e.x - zz.x, d1 = e.y - zz.y;
            float d2 = e.z - zz.z, d3 = e.w - zz.w;
            s = fmaf(d0,d0,s); s = fmaf(d1,d1,s);
            s = fmaf(d2,d2,s); s = fmaf(d3,d3,s);
        }
        g_part[t0+t] = s;
    }

    float w[64];
#pragma unroll
    for (int c4=0;c4<16;c4++){
        float4 ww = *(const float4*)(wsm + tid*WPROW + c4*16);
        w[4*c4+0]=ww.x; w[4*c4+1]=ww.y; w[4*c4+2]=ww.z; w[4*c4+3]=ww.w;
    }
    float bpv = bp[tid];
    for (int t=0;t<128;t++){
        float a0=0.f,a1=0.f,a2=0.f,a3=0.f;
#pragma unroll
        for (int c4=0;c4<16;c4++){
            float4 e = *(const float4*)(esm + t*WPROW + c4*16);
            a0 = fmaf(w[4*c4+0], e.x, a0);
            a1 = fmaf(w[4*c4+1], e.y, a1);
            a2 = fmaf(w[4*c4+2], e.z, a2);
            a3 = fmaf(w[4*c4+3], e.w, a3);
        }
        d_out[(t0+t)*DIMQ + tid] = (a0+a1)+(a2+a3) + bpv;
    }
}

// ---------------------------------------------------------------------------
// Kernel 7: loss = m*(1+BETA)
// ---------------------------------------------------------------------------
__global__ void k_loss(float* __restrict__ d_out, int out_size){
    __shared__ float sh[256];
    int tid = threadIdx.x;
    float s = 0.f;
    for (int i=tid;i<NTOK;i+=256) s += g_part[i];
    sh[tid] = s;
    __syncthreads();
    for (int o=128;o>0;o>>=1){
        if (tid < o) sh[tid] += sh[tid+o];
        __syncthreads();
    }
    if (tid==0 && out_size > OUT_OFF_LOSS){
        float m = sh[0] / (float)(NTOK*CD);
        d_out[OUT_OFF_LOSS] = m + 0.25f*m;
    }
}

// ---------------------------------------------------------------------------
extern "C" void kernel_launch(void* const* d_in, const int* in_sizes, int n_in,
                              void* d_out, int out_size){
    const float* z   = (const float*)d_in[0];
    const float* Wq  = (const float*)d_in[1];
    const float* bq  = (const float*)d_in[2];
    const float* emb = (const float*)d_in[3];
    const float* Wp  = (const float*)d_in[4];
    const float* bp  = (const float*)d_in[5];
    float* out = (float*)d_out;
    (void)in_sizes; (void)n_in;

    static int attr_done = 0;
    if (!attr_done){
        cudaFuncSetAttribute(k_zp,     cudaFuncAttributeMaxDynamicSharedMemorySize, SMEM_ZP);
        cudaFuncSetAttribute(k_filter, cudaFuncAttributeMaxDynamicSharedMemorySize, SMEM_F);
        cudaFuncSetAttribute(k_out,    cudaFuncAttributeMaxDynamicSharedMemorySize, SMEM_KO);
        attr_done = 1;
    }

    dim3 gf(NTOK/TILE_M, FSPL);                        // 64 x 4 = 256 CTAs
    k_zp<<<NTOK/64, 256, SMEM_ZP>>>(z, Wq, bq);        // 0
    k_B<<<NK/256, 256>>>(emb);                         // 1 (+ inits)
    k_nop<<<1, 32>>>();                                // 2
    k_filter<<<gf, 256, SMEM_F>>>();                   // 3 (profiled)
    k_select<<<NTOK/8, 256>>>();                       // 4
    k_rescore<<<256, 256>>>(emb);                      // 5
    k_fin<<<NTOK/256, 256>>>(out, out_size);           // 6
    k_out<<<NTOK/128, 256, SMEM_KO>>>(emb, Wp, bp, out);
    k_loss<<<1, 256>>>(out, out_size);
}

// round 13
// speedup vs baseline: 35.4501x; 1.0730x over previous
#include <cuda_runtime.h>
#include <cuda_bf16.h>
#include <cstdint>

#define NTOK 8192
#define DIMQ 256
#define CD   64
#define NK   16384

#define OUT_OFF_IDX  (NTOK*DIMQ)
#define OUT_OFF_LOSS (NTOK*DIMQ + NTOK)

// ---------------- filter geometry ----------------
#define TILE_M 128             // tokens per CTA (4 warps x 32)
#define TILE_N 128             // codes per staged tile
#define FSPL   4               // K splits (grid.y) -> 256 CTAs (2/SM)
#define KRANGE (NK/FSPL)       // 4096
#define NCT    (KRANGE/TILE_N) // 32 code tiles per CTA
#define NGRP   (NK/32)         // 512 code-groups of 32
#define MARGIN 2e-4f
#define LISTCAP (1<<20)

// filter smem
#define OFF_ZH  0                      // 128 x 128B (SW128)    = 16384
#define OFF_E   16384                  // 2 x 128 x 128B        = 32768
#define OFF_BKQ 49152                  // 2 x 128 floats        = 1024
#define SMEM_F  50176

// ---- k_zp smem ----
#define ZROW 1040
#define SMEM_ZP (64*ZROW*2)
// ---- k_out smem ----
#define WPROW 272
#define SMEM_KO (256*WPROW + 128*WPROW)

#define SWZ128(o) ((o) ^ (((o) >> 3) & 0x70))

// ---------------- scratch ----------------
__device__ float g_zp[NTOK*CD];
__device__ float g_A[NTOK];
__device__ float g_Bk[NK];
__device__ __nv_bfloat16 g_zph[NTOK*CD];
__device__ __nv_bfloat16 g_eh[NK*CD];
__device__ float g_gmax[NTOK*NGRP];
__device__ unsigned long long g_best[NTOK];
__device__ int g_list[LISTCAP];
__device__ int g_cnt;
__device__ int g_flag;
__device__ int g_idx[NTOK];
__device__ float g_part[NTOK];

__device__ __forceinline__ uint32_t smem_u32(const void* p){
    uint32_t a;
    asm("{ .reg .u64 t; cvta.to.shared.u64 t, %1; cvt.u32.u64 %0, t; }"
        : "=r"(a) : "l"(p));
    return a;
}
__device__ __forceinline__ void ldsm4(uint32_t& r0, uint32_t& r1,
                                      uint32_t& r2, uint32_t& r3, uint32_t addr){
    asm volatile("ldmatrix.sync.aligned.m8n8.x4.shared.b16 {%0,%1,%2,%3}, [%4];"
        : "=r"(r0), "=r"(r1), "=r"(r2), "=r"(r3) : "r"(addr));
}
__device__ __forceinline__ void mma16816(float* d, const uint32_t* a,
                                         uint32_t b0, uint32_t b1){
    asm volatile("mma.sync.aligned.m16n8k16.row.col.f32.bf16.bf16.f32 "
        "{%0,%1,%2,%3}, {%4,%5,%6,%7}, {%8,%9}, {%0,%1,%2,%3};"
        : "+f"(d[0]), "+f"(d[1]), "+f"(d[2]), "+f"(d[3])
        : "r"(a[0]), "r"(a[1]), "r"(a[2]), "r"(a[3]), "r"(b0), "r"(b1));
}
__device__ __forceinline__ void cpasync16(uint32_t dst, const void* src){
    asm volatile("cp.async.cg.shared.global [%0], [%1], 16;"
                 :: "r"(dst), "l"(src) : "memory");
}
__device__ __forceinline__ void cpasync4(uint32_t dst, const void* src){
    asm volatile("cp.async.ca.shared.global [%0], [%1], 4;"
                 :: "r"(dst), "l"(src) : "memory");
}
__device__ __forceinline__ void cpcommit(){
    asm volatile("cp.async.commit_group;" ::: "memory");
}
__device__ __forceinline__ void cpwait0(){
    asm volatile("cp.async.wait_group 0;" ::: "memory");
}
__device__ __forceinline__ unsigned int ford(float f){
    unsigned int b = __float_as_uint(f);
    return (b & 0x80000000u) ? ~b : (b | 0x80000000u);
}

// ---------------------------------------------------------------------------
// Kernel 1: zp = z @ Wq^T + bq (strictly-sequential ascending-d chain --
// bit-matching, DO NOT reorder) + A tree (bit-matching) + bf16-hi copy.
// ---------------------------------------------------------------------------
__global__ __launch_bounds__(256) void k_zp(const float* __restrict__ z,
                                            const float* __restrict__ Wq,
                                            const float* __restrict__ bq){
    extern __shared__ char sm[];
    char* wsm = sm;
    char* zsm = sm + 64*ZROW;
    int tid = threadIdx.x;
    int ts = tid >> 6, c = tid & 63;
    int t0 = blockIdx.x * 64;

    const float4* wq4 = (const float4*)Wq;
    const float4* z4  = (const float4*)z;
#pragma unroll
    for (int i=0;i<16;i++){
        int lin = tid + 256*i;
        int r = lin >> 6, q = lin & 63;
        *(float4*)(wsm + r*ZROW + q*16) = wq4[r*64 + q];
        *(float4*)(zsm + r*ZROW + q*16) = z4[(t0+r)*64 + q];
    }
    __syncthreads();

    float acc[16];
#pragma unroll
    for (int i=0;i<16;i++) acc[i] = 0.f;
#pragma unroll 4
    for (int k4=0;k4<64;k4++){
        float4 w = *(const float4*)(wsm + c*ZROW + k4*16);
#pragma unroll
        for (int i=0;i<16;i++){
            float4 zz = *(const float4*)(zsm + (ts*16+i)*ZROW + k4*16);
            acc[i] = fmaf(w.x, zz.x, acc[i]);
            acc[i] = fmaf(w.y, zz.y, acc[i]);
            acc[i] = fmaf(w.z, zz.z, acc[i]);
            acc[i] = fmaf(w.w, zz.w, acc[i]);
        }
    }
    float bqc = bq[c];
    float vv[16];
#pragma unroll
    for (int i=0;i<16;i++){
        float v = acc[i] + bqc;
        int gt = t0 + ts*16 + i;
        g_zp[gt*CD + c] = v;
        g_zph[gt*CD + c] = __float2bfloat16(v);
        vv[i] = v*v;
    }
    __syncthreads();
#pragma unroll
    for (int i=0;i<16;i++)
        *(float*)(zsm + (ts*16+i)*ZROW + c*4) = vv[i];
    __syncthreads();
    int l = tid & 31, w = tid >> 5;
#pragma unroll
    for (int tt=0;tt<8;tt++){
        int t = w*8 + tt;
        float s = *(float*)(zsm + t*ZROW + l*4) + *(float*)(zsm + t*ZROW + (l+32)*4);
        s += __shfl_down_sync(0xffffffffu, s, 16);
        s += __shfl_down_sync(0xffffffffu, s, 8);
        s += __shfl_down_sync(0xffffffffu, s, 4);
        s += __shfl_down_sync(0xffffffffu, s, 2);
        s += __shfl_down_sync(0xffffffffu, s, 1);
        if (l==0) g_A[t0+t] = s;
    }
}

// ---------------------------------------------------------------------------
// Kernel 2: B[k] = ||emb_k||^2 + bf16-hi copy + per-launch scratch inits
// ---------------------------------------------------------------------------
__global__ void k_B(const float* __restrict__ emb){
    int k = blockIdx.x*blockDim.x + threadIdx.x;
    if (k == 0){ g_cnt = 0; g_flag = 0; }
    if (k < NTOK) g_best[k] = 0xFFFFFFFFFFFFFFFFULL;
    if (k >= NK) return;
    const float4* e4 = (const float4*)(emb + k*CD);
    __nv_bfloat162* eh2 = (__nv_bfloat162*)(g_eh + k*CD);
    float s0=0.f,s1=0.f,s2=0.f,s3=0.f;
#pragma unroll
    for (int i=0;i<16;i++){
        float4 e = e4[i];
        s0=fmaf(e.x,e.x,s0); s1=fmaf(e.y,e.y,s1);
        s2=fmaf(e.z,e.z,s2); s3=fmaf(e.w,e.w,s3);
        eh2[2*i]   = __nv_bfloat162(__float2bfloat16(e.x), __float2bfloat16(e.y));
        eh2[2*i+1] = __nv_bfloat162(__float2bfloat16(e.z), __float2bfloat16(e.w));
    }
    g_Bk[k] = (s0+s1)+(s2+s3);
}

__global__ void k_nop(){}

// ---------------------------------------------------------------------------
// Kernel 3: filter.  4 warps x (32 tokens x 128 codes) per CTA; cp.async
// double-buffered e tiles.  Writes per-(token, 32-code-group) max of
// m-hat = 2*ab - B to g_gmax.  Branch-free epilogue.
// ---------------------------------------------------------------------------
__global__ __launch_bounds__(128, 2) void k_filter(){
    extern __shared__ char sm[];
    uint32_t sbase = smem_u32(sm);
    float (*Bk_s)[128] = (float (*)[128])(sm + OFF_BKQ);
    int tid = threadIdx.x;
    int wid = tid >> 5, lane = tid & 31;
    int g   = lane >> 2, tig = lane & 3;
    int t0 = blockIdx.x * TILE_M;
    int kbase0 = blockIdx.y * KRANGE;

    const uint4* zh4 = (const uint4*)g_zph;
    const uint4* eh4 = (const uint4*)g_eh;

    // ---- stage zp_hi tile [128 tok x 128B] (plain stores) ----
#pragma unroll
    for (int i=0;i<8;i++){
        int lin = tid + 128*i;              // 0..1023
        int r = lin >> 3, c8 = lin & 7;
        *(uint4*)(sm + OFF_ZH + SWZ128(r*128 + c8*16)) = zh4[(t0+r)*8 + c8];
    }
    // ---- cp.async e tile 0 + Bk into buf 0 ----
#pragma unroll
    for (int i=0;i<8;i++){
        int lin = tid + 128*i;
        int r = lin >> 3, c8 = lin & 7;
        cpasync16(sbase + OFF_E + SWZ128(r*128 + c8*16), &eh4[(kbase0 + r)*8 + c8]);
    }
    cpasync4(sbase + OFF_BKQ + tid*4, &g_Bk[kbase0 + tid]);
    cpcommit();
    cpwait0();
    __syncthreads();

    // ---- A fragments: 2 m16 tiles per warp, once per CTA ----
    uint32_t afr[4][2][4];
    {
        int acolh = ((lane >> 4) & 1)*16;
#pragma unroll
        for (int mt=0; mt<2; mt++){
            int arow = wid*32 + mt*16 + (lane & 7) + ((lane >> 3) & 1)*8;
#pragma unroll
            for (int ks=0;ks<4;ks++){
                uint32_t addr = sbase + OFF_ZH + SWZ128(arow*128 + ks*32 + acolh);
                ldsm4(afr[ks][mt][0], afr[ks][mt][1], afr[ks][mt][2], afr[ks][mt][3], addr);
            }
        }
    }

    int brow = (lane & 7) + ((lane >> 4) & 1)*8;
    int bcolh = ((lane >> 3) & 1)*16;
    int buf = 0;

    for (int it=0; it<NCT; it++){
        // issue next tile into buf^1 (overlaps with MMA below)
        if (it+1 < NCT){
            int kbn = kbase0 + (it+1)*TILE_N;
            char* eb = sm + OFF_E + (buf^1)*16384;
#pragma unroll
            for (int i=0;i<8;i++){
                int lin = tid + 128*i;
                int r = lin >> 3, c8 = lin & 7;
                cpasync16(sbase + (uint32_t)(eb - sm) + SWZ128(r*128 + c8*16),
                          &eh4[(kbn + r)*8 + c8]);
            }
            cpasync4(sbase + OFF_BKQ + (buf^1)*512 + tid*4, &g_Bk[kbn + tid]);
            cpcommit();
        }

        // ---- MMA: 32 tokens x 128 codes per warp ----
        float dacc[2][16][4];
#pragma unroll
        for (int mt=0;mt<2;mt++)
#pragma unroll
            for (int nt=0;nt<16;nt++){
                dacc[mt][nt][0]=0.f; dacc[mt][nt][1]=0.f;
                dacc[mt][nt][2]=0.f; dacc[mt][nt][3]=0.f;
            }
        uint32_t ebase = sbase + OFF_E + buf*16384;
#pragma unroll
        for (int ks=0;ks<4;ks++){
#pragma unroll
            for (int p=0;p<8;p++){
                uint32_t b0,b1,b2,b3;
                uint32_t addr = ebase + SWZ128((p*16 + brow)*128 + ks*32 + bcolh);
                ldsm4(b0,b1,b2,b3, addr);
                mma16816(dacc[0][2*p],   afr[ks][0], b0, b1);
                mma16816(dacc[0][2*p+1], afr[ks][0], b2, b3);
                mma16816(dacc[1][2*p],   afr[ks][1], b0, b1);
                mma16816(dacc[1][2*p+1], afr[ks][1], b2, b3);
            }
        }

        // ---- epilogue: per-32-code-group maxes for 4 token rows ----
        float gm[4][4];                    // [token row][group]
#pragma unroll
        for (int g32=0; g32<4; g32++){
#pragma unroll
            for (int mt=0; mt<2; mt++){
                float a0 = -3.402823466e38f, b0 = -3.402823466e38f;
#pragma unroll
                for (int q=0;q<4;q++){
                    int nt = g32*4 + q;
                    float2 bk = *(const float2*)&Bk_s[buf][nt*8 + 2*tig];
                    a0 = fmaxf(a0, fmaxf(fmaf(2.f, dacc[mt][nt][0], -bk.x),
                                         fmaf(2.f, dacc[mt][nt][1], -bk.y)));
                    b0 = fmaxf(b0, fmaxf(fmaf(2.f, dacc[mt][nt][2], -bk.x),
                                         fmaf(2.f, dacc[mt][nt][3], -bk.y)));
                }
                a0 = fmaxf(a0, __shfl_xor_sync(0xffffffffu, a0, 1));
                a0 = fmaxf(a0, __shfl_xor_sync(0xffffffffu, a0, 2));
                b0 = fmaxf(b0, __shfl_xor_sync(0xffffffffu, b0, 1));
                b0 = fmaxf(b0, __shfl_xor_sync(0xffffffffu, b0, 2));
                gm[mt*2][g32] = a0; gm[mt*2+1][g32] = b0;
            }
        }
        if (tig == 0){
            int gidx = blockIdx.y*(NCT*4) + it*4;
#pragma unroll
            for (int tr=0; tr<4; tr++){
                int tok = t0 + wid*32 + g + tr*8;
#pragma unroll
                for (int g32=0; g32<4; g32++)
                    g_gmax[tok*NGRP + gidx + g32] = gm[tr][g32];
            }
        }
        if (it+1 < NCT) cpwait0();
        __syncthreads();
        buf ^= 1;
    }
}

// ---------------------------------------------------------------------------
// Kernel 4: select -- per-token scan of 512 group maxes; append qualifying
// groups (>= M - MARGIN) to global list.  Warp per token.
// ---------------------------------------------------------------------------
__global__ __launch_bounds__(256) void k_select(){
    int wid = threadIdx.x >> 5, lane = threadIdx.x & 31;
    int t = blockIdx.x*8 + wid;
    const float4* gm4 = (const float4*)(g_gmax + t*NGRP);
    float4 v[4];
    float mx = -3.402823466e38f;
#pragma unroll
    for (int i=0;i<4;i++){
        v[i] = gm4[lane + 32*i];
        mx = fmaxf(mx, fmaxf(fmaxf(v[i].x, v[i].y), fmaxf(v[i].z, v[i].w)));
    }
#pragma unroll
    for (int o=16;o>0;o>>=1)
        mx = fmaxf(mx, __shfl_xor_sync(0xffffffffu, mx, o));
    float thr = mx - MARGIN;
#pragma unroll
    for (int i=0;i<4;i++){
        int gb = (lane + 32*i)*4;
        float c[4] = {v[i].x, v[i].y, v[i].z, v[i].w};
#pragma unroll
        for (int j=0;j<4;j++){
            if (c[j] >= thr){
                int p = atomicAdd(&g_cnt, 1);
                if (p < LISTCAP) g_list[p] = (t << 9) | (gb + j);
                else g_flag = 1;
            }
        }
    }
}

// ---------------------------------------------------------------------------
// Kernel 5: exact rescore.  Warp per list entry; lane per code in group.
// Strictly-sequential ascending-c fp32 chain + reference score rounding.
// u64 atomicMin == first-index tie-break.
// ---------------------------------------------------------------------------
__global__ __launch_bounds__(256) void k_rescore(const float* __restrict__ emb){
    int gw = (blockIdx.x*blockDim.x + threadIdx.x) >> 5;
    int lane = threadIdx.x & 31;
    int nw = (gridDim.x*blockDim.x) >> 5;
    if (!g_flag){
        int cnt = g_cnt; if (cnt > LISTCAP) cnt = LISTCAP;
        for (int i = gw; i < cnt; i += nw){
            int pk = g_list[i];
            int t = pk >> 9, grp = pk & 511;
            int k = grp*32 + lane;
            const float4* zp4 = (const float4*)(g_zp + t*CD);
            const float4* e4  = (const float4*)(emb + k*CD);
            float ab = 0.f;
#pragma unroll
            for (int c4=0;c4<16;c4++){
                float4 zz = zp4[c4]; float4 e = e4[c4];
                ab = fmaf(zz.x, e.x, ab);
                ab = fmaf(zz.y, e.y, ab);
                ab = fmaf(zz.z, e.z, ab);
                ab = fmaf(zz.w, e.w, ab);
            }
            float s = (g_A[t] + g_Bk[k]) - 2.0f*ab;
            unsigned long long u = ((unsigned long long)ford(s) << 32) | (unsigned)k;
#pragma unroll
            for (int o=16;o>0;o>>=1)
                u = min(u, __shfl_xor_sync(0xffffffffu, u, o));
            if (lane == 0) atomicMin(&g_best[t], u);
        }
    } else {
        for (int t = gw; t < NTOK; t += nw){
            const float4* zp4 = (const float4*)(g_zp + t*CD);
            float A = g_A[t];
            float bv = 3.402823466e38f; int bi = 0x7fffffff;
            for (int k=lane; k<NK; k+=32){
                const float4* e4 = (const float4*)(emb + k*CD);
                float ab = 0.f;
#pragma unroll
                for (int c4=0;c4<16;c4++){
                    float4 zz = zp4[c4]; float4 e = e4[c4];
                    ab = fmaf(zz.x, e.x, ab);
                    ab = fmaf(zz.y, e.y, ab);
                    ab = fmaf(zz.z, e.z, ab);
                    ab = fmaf(zz.w, e.w, ab);
                }
                float s = (A + g_Bk[k]) - 2.0f*ab;
                if (s < bv || (s == bv && k < bi)){ bv = s; bi = k; }
            }
            unsigned long long u = ((unsigned long long)ford(bv) << 32) | (unsigned)bi;
#pragma unroll
            for (int o=16;o>0;o>>=1)
                u = min(u, __shfl_xor_sync(0xffffffffu, u, o));
            if (lane == 0) atomicMin(&g_best[t], u);
        }
    }
}

// ---------------------------------------------------------------------------
// Kernel 5.5: finalize indices
// ---------------------------------------------------------------------------
__global__ void k_fin(float* __restrict__ d_out, int out_size){
    int t = blockIdx.x*blockDim.x + threadIdx.x;
    if (t >= NTOK) return;
    int bi = (int)(unsigned)(g_best[t] & 0xFFFFFFFFULL);
    g_idx[t] = bi;
    if (out_size > OUT_OFF_IDX + t) d_out[OUT_OFF_IDX + t] = (float)bi;
}

// ---------------------------------------------------------------------------
// Kernel 6: out = emb[idx] @ Wp^T + bp + commit-loss partials
// ---------------------------------------------------------------------------
__global__ __launch_bounds__(256) void k_out(const float* __restrict__ emb,
                                             const float* __restrict__ Wp,
                                             const float* __restrict__ bp,
                                             float* __restrict__ d_out){
    extern __shared__ char sm[];
    char* wsm = sm;
    char* esm = sm + 256*WPROW;
    int tid = threadIdx.x;
    int t0 = blockIdx.x * 128;

    const float4* wp4 = (const float4*)Wp;
    const float4* em4 = (const float4*)emb;
#pragma unroll
    for (int i=0;i<16;i++){
        int lin = tid + 256*i;
        int d = lin >> 4, c4 = lin & 15;
        *(float4*)(wsm + d*WPROW + c4*16) = wp4[d*16 + c4];
    }
#pragma unroll
    for (int i=0;i<8;i++){
        int lin = tid + 256*i;
        int t = lin >> 4, c4 = lin & 15;
        int idx = g_idx[t0+t];
        *(float4*)(esm + t*WPROW + c4*16) = em4[idx*16 + c4];
    }
    __syncthreads();

    if (tid < 128){
        int t = tid;
        const float4* zq = (const float4*)(g_zp + (t0+t)*CD);
        float s = 0.f;
#pragma unroll
        for (int c4=0;c4<16;c4++){
            float4 e = *(const float4*)(esm + t*WPROW + c4*16);
            float4 zz = zq[c4];
            float d0 = e.x - zz.x, d1 = e.y - zz.y;
            float d2 = e.z - zz.z, d3 = e.w - zz.w;
            s = fmaf(d0,d0,s); s = fmaf(d1,d1,s);
            s = fmaf(d2,d2,s); s = fmaf(d3,d3,s);
        }
        g_part[t0+t] = s;
    }

    float w[64];
#pragma unroll
    for (int c4=0;c4<16;c4++){
        float4 ww = *(const float4*)(wsm + tid*WPROW + c4*16);
        w[4*c4+0]=ww.x; w[4*c4+1]=ww.y; w[4*c4+2]=ww.z; w[4*c4+3]=ww.w;
    }
    float bpv = bp[tid];
    for (int t=0;t<128;t++){
        float a0=0.f,a1=0.f,a2=0.f,a3=0.f;
#pragma unroll
        for (int c4=0;c4<16;c4++){
            float4 e = *(const float4*)(esm + t*WPROW + c4*16);
            a0 = fmaf(w[4*c4+0], e.x, a0);
            a1 = fmaf(w[4*c4+1], e.y, a1);
            a2 = fmaf(w[4*c4+2], e.z, a2);
            a3 = fmaf(w[4*c4+3], e.w, a3);
        }
        d_out[(t0+t)*DIMQ + tid] = (a0+a1)+(a2+a3) + bpv;
    }
}

// ---------------------------------------------------------------------------
// Kernel 7: loss = m*(1+BETA)
// ---------------------------------------------------------------------------
__global__ void k_loss(float* __restrict__ d_out, int out_size){
    __shared__ float sh[256];
    int tid = threadIdx.x;
    float s = 0.f;
    for (int i=tid;i<NTOK;i+=256) s += g_part[i];
    sh[tid] = s;
    __syncthreads();
    for (int o=128;o>0;o>>=1){
        if (tid < o) sh[tid] += sh[tid+o];
        __syncthreads();
    }
    if (tid==0 && out_size > OUT_OFF_LOSS){
        float m = sh[0] / (float)(NTOK*CD);
        d_out[OUT_OFF_LOSS] = m + 0.25f*m;
    }
}

// ---------------------------------------------------------------------------
extern "C" void kernel_launch(void* const* d_in, const int* in_sizes, int n_in,
                              void* d_out, int out_size){
    const float* z   = (const float*)d_in[0];
    const float* Wq  = (const float*)d_in[1];
    const float* bq  = (const float*)d_in[2];
    const float* emb = (const float*)d_in[3];
    const float* Wp  = (const float*)d_in[4];
    const float* bp  = (const float*)d_in[5];
    float* out = (float*)d_out;
    (void)in_sizes; (void)n_in;

    static int attr_done = 0;
    if (!attr_done){
        cudaFuncSetAttribute(k_zp,     cudaFuncAttributeMaxDynamicSharedMemorySize, SMEM_ZP);
        cudaFuncSetAttribute(k_filter, cudaFuncAttributeMaxDynamicSharedMemorySize, SMEM_F);
        cudaFuncSetAttribute(k_out,    cudaFuncAttributeMaxDynamicSharedMemorySize, SMEM_KO);
        attr_done = 1;
    }

    dim3 gf(NTOK/TILE_M, FSPL);                        // 64 x 4 = 256 CTAs, 2/SM
    k_zp<<<NTOK/64, 256, SMEM_ZP>>>(z, Wq, bq);        // 0
    k_B<<<NK/256, 256>>>(emb);                         // 1 (+ inits)
    k_nop<<<1, 32>>>();                                // 2
    k_filter<<<gf, 128, SMEM_F>>>();                   // 3 (profiled)
    k_select<<<NTOK/8, 256>>>();                       // 4
    k_rescore<<<256, 256>>>(emb);                      // 5
    k_fin<<<NTOK/256, 256>>>(out, out_size);           // 6
    k_out<<<NTOK/128, 256, SMEM_KO>>>(emb, Wp, bp, out);
    k_loss<<<1, 256>>>(out, out_size);
}

// round 14
// speedup vs baseline: 40.4021x; 1.1397x over previous
#include <cuda_runtime.h>
#include <cuda_bf16.h>
#include <cstdint>

#define NTOK 8192
#define DIMQ 256
#define CD   64
#define NK   16384

#define OUT_OFF_IDX  (NTOK*DIMQ)
#define OUT_OFF_LOSS (NTOK*DIMQ + NTOK)

// ---------------- filter geometry ----------------
#define TILE_M 128             // tokens per CTA (4 warps x 32)
#define TILE_N 128             // codes per staged tile
#define FSPL   4               // K splits (grid.y) -> 256 CTAs (2/SM)
#define KRANGE (NK/FSPL)       // 4096
#define NCT    (KRANGE/TILE_N) // 32 code tiles per CTA
#define NGRP   (NK/32)         // 512 code-groups of 32
#define MARGIN 2e-4f

// filter smem
#define OFF_ZH  0                      // 128 x 128B (SW128)    = 16384
#define OFF_E   16384                  // 2 x 128 x 128B        = 32768
#define OFF_BKQ 49152                  // 2 x 128 floats        = 1024
#define SMEM_F  50176

// ---- k_zp smem ----
#define ZROW 1040
#define SMEM_ZP (64*ZROW*2)
// ---- k_out smem ----
#define WPROW 272
#define SMEM_KO (256*WPROW + 128*WPROW)

#define SWZ128(o) ((o) ^ (((o) >> 3) & 0x70))

// ---------------- scratch ----------------
__device__ float g_zp[NTOK*CD];
__device__ float g_A[NTOK];
__device__ float g_Bk[NK];
__device__ __nv_bfloat16 g_zph[NTOK*CD];
__device__ __nv_bfloat16 g_eh[NK*CD];
__device__ float g_gmax[NTOK*NGRP];
__device__ int   g_idx[NTOK];
__device__ float g_part[NTOK];

__device__ __forceinline__ uint32_t smem_u32(const void* p){
    uint32_t a;
    asm("{ .reg .u64 t; cvta.to.shared.u64 t, %1; cvt.u32.u64 %0, t; }"
        : "=r"(a) : "l"(p));
    return a;
}
__device__ __forceinline__ void ldsm4(uint32_t& r0, uint32_t& r1,
                                      uint32_t& r2, uint32_t& r3, uint32_t addr){
    asm volatile("ldmatrix.sync.aligned.m8n8.x4.shared.b16 {%0,%1,%2,%3}, [%4];"
        : "=r"(r0), "=r"(r1), "=r"(r2), "=r"(r3) : "r"(addr));
}
__device__ __forceinline__ void mma16816(float* d, const uint32_t* a,
                                         uint32_t b0, uint32_t b1){
    asm volatile("mma.sync.aligned.m16n8k16.row.col.f32.bf16.bf16.f32 "
        "{%0,%1,%2,%3}, {%4,%5,%6,%7}, {%8,%9}, {%0,%1,%2,%3};"
        : "+f"(d[0]), "+f"(d[1]), "+f"(d[2]), "+f"(d[3])
        : "r"(a[0]), "r"(a[1]), "r"(a[2]), "r"(a[3]), "r"(b0), "r"(b1));
}
__device__ __forceinline__ void cpasync16(uint32_t dst, const void* src){
    asm volatile("cp.async.cg.shared.global [%0], [%1], 16;"
                 :: "r"(dst), "l"(src) : "memory");
}
__device__ __forceinline__ void cpasync4(uint32_t dst, const void* src){
    asm volatile("cp.async.ca.shared.global [%0], [%1], 4;"
                 :: "r"(dst), "l"(src) : "memory");
}
__device__ __forceinline__ void cpcommit(){
    asm volatile("cp.async.commit_group;" ::: "memory");
}
__device__ __forceinline__ void cpwait0(){
    asm volatile("cp.async.wait_group 0;" ::: "memory");
}
__device__ __forceinline__ unsigned int ford(float f){
    unsigned int b = __float_as_uint(f);
    return (b & 0x80000000u) ? ~b : (b | 0x80000000u);
}

// ---------------------------------------------------------------------------
// Kernel 1: zp = z @ Wq^T + bq (strictly-sequential ascending-d chain --
// bit-matching, DO NOT reorder) + A tree (bit-matching) + bf16-hi copy.
// ---------------------------------------------------------------------------
__global__ __launch_bounds__(256) void k_zp(const float* __restrict__ z,
                                            const float* __restrict__ Wq,
                                            const float* __restrict__ bq){
    extern __shared__ char sm[];
    char* wsm = sm;
    char* zsm = sm + 64*ZROW;
    int tid = threadIdx.x;
    int ts = tid >> 6, c = tid & 63;
    int t0 = blockIdx.x * 64;

    const float4* wq4 = (const float4*)Wq;
    const float4* z4  = (const float4*)z;
#pragma unroll
    for (int i=0;i<16;i++){
        int lin = tid + 256*i;
        int r = lin >> 6, q = lin & 63;
        *(float4*)(wsm + r*ZROW + q*16) = wq4[r*64 + q];
        *(float4*)(zsm + r*ZROW + q*16) = z4[(t0+r)*64 + q];
    }
    __syncthreads();

    float acc[16];
#pragma unroll
    for (int i=0;i<16;i++) acc[i] = 0.f;
#pragma unroll 4
    for (int k4=0;k4<64;k4++){
        float4 w = *(const float4*)(wsm + c*ZROW + k4*16);
#pragma unroll
        for (int i=0;i<16;i++){
            float4 zz = *(const float4*)(zsm + (ts*16+i)*ZROW + k4*16);
            acc[i] = fmaf(w.x, zz.x, acc[i]);
            acc[i] = fmaf(w.y, zz.y, acc[i]);
            acc[i] = fmaf(w.z, zz.z, acc[i]);
            acc[i] = fmaf(w.w, zz.w, acc[i]);
        }
    }
    float bqc = bq[c];
    float vv[16];
#pragma unroll
    for (int i=0;i<16;i++){
        float v = acc[i] + bqc;
        int gt = t0 + ts*16 + i;
        g_zp[gt*CD + c] = v;
        g_zph[gt*CD + c] = __float2bfloat16(v);
        vv[i] = v*v;
    }
    __syncthreads();
#pragma unroll
    for (int i=0;i<16;i++)
        *(float*)(zsm + (ts*16+i)*ZROW + c*4) = vv[i];
    __syncthreads();
    int l = tid & 31, w = tid >> 5;
#pragma unroll
    for (int tt=0;tt<8;tt++){
        int t = w*8 + tt;
        float s = *(float*)(zsm + t*ZROW + l*4) + *(float*)(zsm + t*ZROW + (l+32)*4);
        s += __shfl_down_sync(0xffffffffu, s, 16);
        s += __shfl_down_sync(0xffffffffu, s, 8);
        s += __shfl_down_sync(0xffffffffu, s, 4);
        s += __shfl_down_sync(0xffffffffu, s, 2);
        s += __shfl_down_sync(0xffffffffu, s, 1);
        if (l==0) g_A[t0+t] = s;
    }
}

// ---------------------------------------------------------------------------
// Kernel 2: B[k] = ||emb_k||^2 + bf16-hi copy
// ---------------------------------------------------------------------------
__global__ void k_B(const float* __restrict__ emb){
    int k = blockIdx.x*blockDim.x + threadIdx.x;
    if (k >= NK) return;
    const float4* e4 = (const float4*)(emb + k*CD);
    __nv_bfloat162* eh2 = (__nv_bfloat162*)(g_eh + k*CD);
    float s0=0.f,s1=0.f,s2=0.f,s3=0.f;
#pragma unroll
    for (int i=0;i<16;i++){
        float4 e = e4[i];
        s0=fmaf(e.x,e.x,s0); s1=fmaf(e.y,e.y,s1);
        s2=fmaf(e.z,e.z,s2); s3=fmaf(e.w,e.w,s3);
        eh2[2*i]   = __nv_bfloat162(__float2bfloat16(e.x), __float2bfloat16(e.y));
        eh2[2*i+1] = __nv_bfloat162(__float2bfloat16(e.z), __float2bfloat16(e.w));
    }
    g_Bk[k] = (s0+s1)+(s2+s3);
}

__global__ void k_nop(){}

// ---------------------------------------------------------------------------
// Kernel 3: filter (UNCHANGED from R13 -- known-good 66us).  4 warps x
// (32 tokens x 128 codes) per CTA; cp.async double-buffered e tiles.
// Writes per-(token, 32-code-group) max of m-hat = 2*ab - B to g_gmax.
// ---------------------------------------------------------------------------
__global__ __launch_bounds__(128, 2) void k_filter(){
    extern __shared__ char sm[];
    uint32_t sbase = smem_u32(sm);
    float (*Bk_s)[128] = (float (*)[128])(sm + OFF_BKQ);
    int tid = threadIdx.x;
    int wid = tid >> 5, lane = tid & 31;
    int g   = lane >> 2, tig = lane & 3;
    int t0 = blockIdx.x * TILE_M;
    int kbase0 = blockIdx.y * KRANGE;

    const uint4* zh4 = (const uint4*)g_zph;
    const uint4* eh4 = (const uint4*)g_eh;

#pragma unroll
    for (int i=0;i<8;i++){
        int lin = tid + 128*i;
        int r = lin >> 3, c8 = lin & 7;
        *(uint4*)(sm + OFF_ZH + SWZ128(r*128 + c8*16)) = zh4[(t0+r)*8 + c8];
    }
#pragma unroll
    for (int i=0;i<8;i++){
        int lin = tid + 128*i;
        int r = lin >> 3, c8 = lin & 7;
        cpasync16(sbase + OFF_E + SWZ128(r*128 + c8*16), &eh4[(kbase0 + r)*8 + c8]);
    }
    cpasync4(sbase + OFF_BKQ + tid*4, &g_Bk[kbase0 + tid]);
    cpcommit();
    cpwait0();
    __syncthreads();

    uint32_t afr[4][2][4];
    {
        int acolh = ((lane >> 4) & 1)*16;
#pragma unroll
        for (int mt=0; mt<2; mt++){
            int arow = wid*32 + mt*16 + (lane & 7) + ((lane >> 3) & 1)*8;
#pragma unroll
            for (int ks=0;ks<4;ks++){
                uint32_t addr = sbase + OFF_ZH + SWZ128(arow*128 + ks*32 + acolh);
                ldsm4(afr[ks][mt][0], afr[ks][mt][1], afr[ks][mt][2], afr[ks][mt][3], addr);
            }
        }
    }

    int brow = (lane & 7) + ((lane >> 4) & 1)*8;
    int bcolh = ((lane >> 3) & 1)*16;
    int buf = 0;

    for (int it=0; it<NCT; it++){
        if (it+1 < NCT){
            int kbn = kbase0 + (it+1)*TILE_N;
            char* eb = sm + OFF_E + (buf^1)*16384;
#pragma unroll
            for (int i=0;i<8;i++){
                int lin = tid + 128*i;
                int r = lin >> 3, c8 = lin & 7;
                cpasync16(sbase + (uint32_t)(eb - sm) + SWZ128(r*128 + c8*16),
                          &eh4[(kbn + r)*8 + c8]);
            }
            cpasync4(sbase + OFF_BKQ + (buf^1)*512 + tid*4, &g_Bk[kbn + tid]);
            cpcommit();
        }

        float dacc[2][16][4];
#pragma unroll
        for (int mt=0;mt<2;mt++)
#pragma unroll
            for (int nt=0;nt<16;nt++){
                dacc[mt][nt][0]=0.f; dacc[mt][nt][1]=0.f;
                dacc[mt][nt][2]=0.f; dacc[mt][nt][3]=0.f;
            }
        uint32_t ebase = sbase + OFF_E + buf*16384;
#pragma unroll
        for (int ks=0;ks<4;ks++){
#pragma unroll
            for (int p=0;p<8;p++){
                uint32_t b0,b1,b2,b3;
                uint32_t addr = ebase + SWZ128((p*16 + brow)*128 + ks*32 + bcolh);
                ldsm4(b0,b1,b2,b3, addr);
                mma16816(dacc[0][2*p],   afr[ks][0], b0, b1);
                mma16816(dacc[0][2*p+1], afr[ks][0], b2, b3);
                mma16816(dacc[1][2*p],   afr[ks][1], b0, b1);
                mma16816(dacc[1][2*p+1], afr[ks][1], b2, b3);
            }
        }

        float gm[4][4];
#pragma unroll
        for (int g32=0; g32<4; g32++){
#pragma unroll
            for (int mt=0; mt<2; mt++){
                float a0 = -3.402823466e38f, b0 = -3.402823466e38f;
#pragma unroll
                for (int q=0;q<4;q++){
                    int nt = g32*4 + q;
                    float2 bk = *(const float2*)&Bk_s[buf][nt*8 + 2*tig];
                    a0 = fmaxf(a0, fmaxf(fmaf(2.f, dacc[mt][nt][0], -bk.x),
                                         fmaf(2.f, dacc[mt][nt][1], -bk.y)));
                    b0 = fmaxf(b0, fmaxf(fmaf(2.f, dacc[mt][nt][2], -bk.x),
                                         fmaf(2.f, dacc[mt][nt][3], -bk.y)));
                }
                a0 = fmaxf(a0, __shfl_xor_sync(0xffffffffu, a0, 1));
                a0 = fmaxf(a0, __shfl_xor_sync(0xffffffffu, a0, 2));
                b0 = fmaxf(b0, __shfl_xor_sync(0xffffffffu, b0, 1));
                b0 = fmaxf(b0, __shfl_xor_sync(0xffffffffu, b0, 2));
                gm[mt*2][g32] = a0; gm[mt*2+1][g32] = b0;
            }
        }
        if (tig == 0){
            int gidx = blockIdx.y*(NCT*4) + it*4;
#pragma unroll
            for (int tr=0; tr<4; tr++){
                int tok = t0 + wid*32 + g + tr*8;
#pragma unroll
                for (int g32=0; g32<4; g32++)
                    g_gmax[tok*NGRP + gidx + g32] = gm[tr][g32];
            }
        }
        if (it+1 < NCT) cpwait0();
        __syncthreads();
        buf ^= 1;
    }
}

// ---------------------------------------------------------------------------
// Kernel 4: FUSED select + rescore + finalize.  Warp per token, NO lists,
// NO atomics, NO fallback.  (a) scan 512 group maxes -> mx, thr = mx-MARGIN.
// (b) ballot over qualify predicate; qualifying group index is computed
// directly from the set-bit position.  (c) exact rescore of each qualifying
// group: strictly-sequential ascending-c fp32 chain + reference score
// rounding (bit-matches the passing scoring); lexicographic (s,k) min ==
// first-index tie-break.  Winning group always qualifies (gmax == mx).
// ---------------------------------------------------------------------------
__global__ __launch_bounds__(256) void k_selres(const float* __restrict__ emb,
                                                float* __restrict__ d_out,
                                                int out_size){
    int wid = threadIdx.x >> 5, lane = threadIdx.x & 31;
    int t = blockIdx.x*8 + wid;

    const float4* gm4 = (const float4*)(g_gmax + t*NGRP);
    float4 v[4];
    float mx = -3.402823466e38f;
#pragma unroll
    for (int i=0;i<4;i++){
        v[i] = gm4[lane + 32*i];
        mx = fmaxf(mx, fmaxf(fmaxf(v[i].x, v[i].y), fmaxf(v[i].z, v[i].w)));
    }
#pragma unroll
    for (int o=16;o>0;o>>=1)
        mx = fmaxf(mx, __shfl_xor_sync(0xffffffffu, mx, o));
    float thr = mx - MARGIN;

    // token data register-resident for all rescored groups
    float A = g_A[t];
    float4 zp[16];
    const float4* zp4 = (const float4*)(g_zp + t*CD);
#pragma unroll
    for (int c4=0;c4<16;c4++) zp[c4] = zp4[c4];

    unsigned long long umin = 0xFFFFFFFFFFFFFFFFULL;
#pragma unroll
    for (int i=0;i<4;i++){
        float c[4] = {v[i].x, v[i].y, v[i].z, v[i].w};
#pragma unroll
        for (int j=0;j<4;j++){
            unsigned mask = __ballot_sync(0xffffffffu, c[j] >= thr);
            while (mask){
                int s = __ffs(mask) - 1;
                mask &= mask - 1;
                int grp = (s + 32*i)*4 + j;      // derived from bit position
                int k = grp*32 + lane;
                const float4* e4 = (const float4*)(emb + k*CD);
                float ab = 0.f;
#pragma unroll
                for (int c4=0;c4<16;c4++){
                    float4 e = e4[c4];
                    ab = fmaf(zp[c4].x, e.x, ab);
                    ab = fmaf(zp[c4].y, e.y, ab);
                    ab = fmaf(zp[c4].z, e.z, ab);
                    ab = fmaf(zp[c4].w, e.w, ab);
                }
                float sc = (A + g_Bk[k]) - 2.0f*ab;   // reference rounding
                unsigned long long u =
                    ((unsigned long long)ford(sc) << 32) | (unsigned)k;
                umin = min(umin, u);
            }
        }
    }
#pragma unroll
    for (int o=16;o>0;o>>=1)
        umin = min(umin, __shfl_xor_sync(0xffffffffu, umin, o));
    if (lane == 0){
        int bi = (int)(unsigned)(umin & 0xFFFFFFFFULL);
        g_idx[t] = bi;
        if (out_size > OUT_OFF_IDX + t) d_out[OUT_OFF_IDX + t] = (float)bi;
    }
}

// ---------------------------------------------------------------------------
// Kernel 5: out = emb[idx] @ Wp^T + bp + commit-loss partials
// ---------------------------------------------------------------------------
__global__ __launch_bounds__(256) void k_out(const float* __restrict__ emb,
                                             const float* __restrict__ Wp,
                                             const float* __restrict__ bp,
                                             float* __restrict__ d_out){
    extern __shared__ char sm[];
    char* wsm = sm;
    char* esm = sm + 256*WPROW;
    int tid = threadIdx.x;
    int t0 = blockIdx.x * 128;

    const float4* wp4 = (const float4*)Wp;
    const float4* em4 = (const float4*)emb;
#pragma unroll
    for (int i=0;i<16;i++){
        int lin = tid + 256*i;
        int d = lin >> 4, c4 = lin & 15;
        *(float4*)(wsm + d*WPROW + c4*16) = wp4[d*16 + c4];
    }
#pragma unroll
    for (int i=0;i<8;i++){
        int lin = tid + 256*i;
        int t = lin >> 4, c4 = lin & 15;
        int idx = g_idx[t0+t];
        *(float4*)(esm + t*WPROW + c4*16) = em4[idx*16 + c4];
    }
    __syncthreads();

    if (tid < 128){
        int t = tid;
        const float4* zq = (const float4*)(g_zp + (t0+t)*CD);
        float s = 0.f;
#pragma unroll
        for (int c4=0;c4<16;c4++){
            float4 e = *(const float4*)(esm + t*WPROW + c4*16);
            float4 zz = zq[c4];
            float d0 = e.x - zz.x, d1 = e.y - zz.y;
            float d2 = e.z - zz.z, d3 = e.w - zz.w;
            s = fmaf(d0,d0,s); s = fmaf(d1,d1,s);
            s = fmaf(d2,d2,s); s = fmaf(d3,d3,s);
        }
        g_part[t0+t] = s;
    }

    float w[64];
#pragma unroll
    for (int c4=0;c4<16;c4++){
        float4 ww = *(const float4*)(wsm + tid*WPROW + c4*16);
        w[4*c4+0]=ww.x; w[4*c4+1]=ww.y; w[4*c4+2]=ww.z; w[4*c4+3]=ww.w;
    }
    float bpv = bp[tid];
    for (int t=0;t<128;t++){
        float a0=0.f,a1=0.f,a2=0.f,a3=0.f;
#pragma unroll
        for (int c4=0;c4<16;c4++){
            float4 e = *(const float4*)(esm + t*WPROW + c4*16);
            a0 = fmaf(w[4*c4+0], e.x, a0);
            a1 = fmaf(w[4*c4+1], e.y, a1);
            a2 = fmaf(w[4*c4+2], e.z, a2);
            a3 = fmaf(w[4*c4+3], e.w, a3);
        }
        d_out[(t0+t)*DIMQ + tid] = (a0+a1)+(a2+a3) + bpv;
    }
}

// ---------------------------------------------------------------------------
// Kernel 6: loss = m*(1+BETA)   (single block -- deterministic)
// ---------------------------------------------------------------------------
__global__ void k_loss(float* __restrict__ d_out, int out_size){
    __shared__ float sh[256];
    int tid = threadIdx.x;
    float s = 0.f;
    for (int i=tid;i<NTOK;i+=256) s += g_part[i];
    sh[tid] = s;
    __syncthreads();
    for (int o=128;o>0;o>>=1){
        if (tid < o) sh[tid] += sh[tid+o];
        __syncthreads();
    }
    if (tid==0 && out_size > OUT_OFF_LOSS){
        float m = sh[0] / (float)(NTOK*CD);
        d_out[OUT_OFF_LOSS] = m + 0.25f*m;
    }
}

// ---------------------------------------------------------------------------
extern "C" void kernel_launch(void* const* d_in, const int* in_sizes, int n_in,
                              void* d_out, int out_size){
    const float* z   = (const float*)d_in[0];
    const float* Wq  = (const float*)d_in[1];
    const float* bq  = (const float*)d_in[2];
    const float* emb = (const float*)d_in[3];
    const float* Wp  = (const float*)d_in[4];
    const float* bp  = (const float*)d_in[5];
    float* out = (float*)d_out;
    (void)in_sizes; (void)n_in;

    static int attr_done = 0;
    if (!attr_done){
        cudaFuncSetAttribute(k_zp,     cudaFuncAttributeMaxDynamicSharedMemorySize, SMEM_ZP);
        cudaFuncSetAttribute(k_filter, cudaFuncAttributeMaxDynamicSharedMemorySize, SMEM_F);
        cudaFuncSetAttribute(k_out,    cudaFuncAttributeMaxDynamicSharedMemorySize, SMEM_KO);
        attr_done = 1;
    }

    dim3 gf(NTOK/TILE_M, FSPL);                        // 64 x 4 = 256 CTAs, 2/SM
    k_zp<<<NTOK/64, 256, SMEM_ZP>>>(z, Wq, bq);        // 0
    k_B<<<NK/256, 256>>>(emb);                         // 1
    k_nop<<<1, 32>>>();                                // 2
    k_filter<<<gf, 128, SMEM_F>>>();                   // 3 (profiled)
    k_selres<<<NTOK/8, 256>>>(emb, out, out_size);     // 4 (fused sel+rescore+fin)
    k_out<<<NTOK/128, 256, SMEM_KO>>>(emb, Wp, bp, out); // 5
    k_loss<<<1, 256>>>(out, out_size);                 // 6
}

// round 15
// speedup vs baseline: 44.4214x; 1.0995x over previous
#include <cuda_runtime.h>
#include <cuda_bf16.h>
#include <cstdint>

#define NTOK 8192
#define DIMQ 256
#define CD   64
#define NK   16384

#define OUT_OFF_IDX  (NTOK*DIMQ)
#define OUT_OFF_LOSS (NTOK*DIMQ + NTOK)

// ---------------- filter geometry ----------------
#define TILE_M 128              // tokens per CTA (4 warps x 32)
#define TILE_N 64               // codes per staged tile
#define KCH    512              // codes per work unit
#define NCHUNK (NK/KCH)         // 32
#define NTILES (NTOK/TILE_M)    // 64
#define NUNITS (NTILES*NCHUNK)  // 2048
#define IT_U   (KCH/TILE_N)     // 8 code-tiles per unit
#define GRID_F 456              // 3 CTAs/SM x 152 SMs
#define NGRP   (NK/32)          // 512 code-groups of 32
#define MARGIN 2e-4f

// filter smem
#define OFF_ZH  0                      // 128 x 128B (SW128)  = 16384
#define OFF_E   16384                  // 2 x 64 x 128B       = 16384
#define OFF_BK  32768                  // 2 x 64 floats       = 512
#define SMEM_F  33280

// ---- k_zp smem ----
#define ZROW 1040
#define SMEM_ZP (64*ZROW*2)
// ---- k_out smem ----
#define WPROW 272
#define SMEM_KO (256*WPROW + 64*WPROW)

#define SWZ128(o) ((o) ^ (((o) >> 3) & 0x70))

// ---------------- scratch ----------------
__device__ float g_zp[NTOK*CD];
__device__ float g_A[NTOK];
__device__ float g_Bk[NK];
__device__ __nv_bfloat16 g_zph[NTOK*CD];
__device__ __nv_bfloat16 g_eh[NK*CD];
__device__ float g_gmax[NTOK*NGRP];
__device__ int   g_idx[NTOK];
__device__ float g_part[NTOK];

__device__ __forceinline__ uint32_t smem_u32(const void* p){
    uint32_t a;
    asm("{ .reg .u64 t; cvta.to.shared.u64 t, %1; cvt.u32.u64 %0, t; }"
        : "=r"(a) : "l"(p));
    return a;
}
__device__ __forceinline__ void ldsm4(uint32_t& r0, uint32_t& r1,
                                      uint32_t& r2, uint32_t& r3, uint32_t addr){
    asm volatile("ldmatrix.sync.aligned.m8n8.x4.shared.b16 {%0,%1,%2,%3}, [%4];"
        : "=r"(r0), "=r"(r1), "=r"(r2), "=r"(r3) : "r"(addr));
}
__device__ __forceinline__ void mma16816(float* d, const uint32_t* a,
                                         uint32_t b0, uint32_t b1){
    asm volatile("mma.sync.aligned.m16n8k16.row.col.f32.bf16.bf16.f32 "
        "{%0,%1,%2,%3}, {%4,%5,%6,%7}, {%8,%9}, {%0,%1,%2,%3};"
        : "+f"(d[0]), "+f"(d[1]), "+f"(d[2]), "+f"(d[3])
        : "r"(a[0]), "r"(a[1]), "r"(a[2]), "r"(a[3]), "r"(b0), "r"(b1));
}
__device__ __forceinline__ void cpasync16(uint32_t dst, const void* src){
    asm volatile("cp.async.cg.shared.global [%0], [%1], 16;"
                 :: "r"(dst), "l"(src) : "memory");
}
__device__ __forceinline__ void cpasync4(uint32_t dst, const void* src){
    asm volatile("cp.async.ca.shared.global [%0], [%1], 4;"
                 :: "r"(dst), "l"(src) : "memory");
}
__device__ __forceinline__ void cpcommit(){
    asm volatile("cp.async.commit_group;" ::: "memory");
}
__device__ __forceinline__ void cpwait0(){
    asm volatile("cp.async.wait_group 0;" ::: "memory");
}
__device__ __forceinline__ unsigned int ford(float f){
    unsigned int b = __float_as_uint(f);
    return (b & 0x80000000u) ? ~b : (b | 0x80000000u);
}

// ---------------------------------------------------------------------------
// Kernel 1: zp = z @ Wq^T + bq (strictly-sequential ascending-d chain --
// bit-matching, DO NOT reorder) + A tree (bit-matching) + bf16-hi copy.
// ---------------------------------------------------------------------------
__global__ __launch_bounds__(256) void k_zp(const float* __restrict__ z,
                                            const float* __restrict__ Wq,
                                            const float* __restrict__ bq){
    extern __shared__ char sm[];
    char* wsm = sm;
    char* zsm = sm + 64*ZROW;
    int tid = threadIdx.x;
    int ts = tid >> 6, c = tid & 63;
    int t0 = blockIdx.x * 64;

    const float4* wq4 = (const float4*)Wq;
    const float4* z4  = (const float4*)z;
#pragma unroll
    for (int i=0;i<16;i++){
        int lin = tid + 256*i;
        int r = lin >> 6, q = lin & 63;
        *(float4*)(wsm + r*ZROW + q*16) = wq4[r*64 + q];
        *(float4*)(zsm + r*ZROW + q*16) = z4[(t0+r)*64 + q];
    }
    __syncthreads();

    float acc[16];
#pragma unroll
    for (int i=0;i<16;i++) acc[i] = 0.f;
#pragma unroll 4
    for (int k4=0;k4<64;k4++){
        float4 w = *(const float4*)(wsm + c*ZROW + k4*16);
#pragma unroll
        for (int i=0;i<16;i++){
            float4 zz = *(const float4*)(zsm + (ts*16+i)*ZROW + k4*16);
            acc[i] = fmaf(w.x, zz.x, acc[i]);
            acc[i] = fmaf(w.y, zz.y, acc[i]);
            acc[i] = fmaf(w.z, zz.z, acc[i]);
            acc[i] = fmaf(w.w, zz.w, acc[i]);
        }
    }
    float bqc = bq[c];
    float vv[16];
#pragma unroll
    for (int i=0;i<16;i++){
        float v = acc[i] + bqc;
        int gt = t0 + ts*16 + i;
        g_zp[gt*CD + c] = v;
        g_zph[gt*CD + c] = __float2bfloat16(v);
        vv[i] = v*v;
    }
    __syncthreads();
#pragma unroll
    for (int i=0;i<16;i++)
        *(float*)(zsm + (ts*16+i)*ZROW + c*4) = vv[i];
    __syncthreads();
    int l = tid & 31, w = tid >> 5;
#pragma unroll
    for (int tt=0;tt<8;tt++){
        int t = w*8 + tt;
        float s = *(float*)(zsm + t*ZROW + l*4) + *(float*)(zsm + t*ZROW + (l+32)*4);
        s += __shfl_down_sync(0xffffffffu, s, 16);
        s += __shfl_down_sync(0xffffffffu, s, 8);
        s += __shfl_down_sync(0xffffffffu, s, 4);
        s += __shfl_down_sync(0xffffffffu, s, 2);
        s += __shfl_down_sync(0xffffffffu, s, 1);
        if (l==0) g_A[t0+t] = s;
    }
}

// ---------------------------------------------------------------------------
// Kernel 2: B[k] = ||emb_k||^2 + bf16-hi copy
// ---------------------------------------------------------------------------
__global__ void k_B(const float* __restrict__ emb){
    int k = blockIdx.x*blockDim.x + threadIdx.x;
    if (k >= NK) return;
    const float4* e4 = (const float4*)(emb + k*CD);
    __nv_bfloat162* eh2 = (__nv_bfloat162*)(g_eh + k*CD);
    float s0=0.f,s1=0.f,s2=0.f,s3=0.f;
#pragma unroll
    for (int i=0;i<16;i++){
        float4 e = e4[i];
        s0=fmaf(e.x,e.x,s0); s1=fmaf(e.y,e.y,s1);
        s2=fmaf(e.z,e.z,s2); s3=fmaf(e.w,e.w,s3);
        eh2[2*i]   = __nv_bfloat162(__float2bfloat16(e.x), __float2bfloat16(e.y));
        eh2[2*i+1] = __nv_bfloat162(__float2bfloat16(e.z), __float2bfloat16(e.w));
    }
    g_Bk[k] = (s0+s1)+(s2+s3);
}

// ---------------------------------------------------------------------------
// Kernel 3: filter -- grid-strided units, 3 CTAs/SM (12 warps).  Unit =
// (token-tile 128, 512-code chunk); 8 double-buffered 64-code e tiles.
// Warp tile 32 tokens x 64 codes (dacc 64 regs).  Same m-hat numerics and
// g_gmax layout as the passing R13/R14 filter.
// ---------------------------------------------------------------------------
__global__ __launch_bounds__(128, 3) void k_filter(){
    extern __shared__ char sm[];
    uint32_t sbase = smem_u32(sm);
    float (*Bk_s)[64] = (float (*)[64])(sm + OFF_BK);
    int tid = threadIdx.x;
    int wid = tid >> 5, lane = tid & 31;
    int g   = lane >> 2, tig = lane & 3;

    const uint4* zh4 = (const uint4*)g_zph;
    const uint4* eh4 = (const uint4*)g_eh;
    int brow = (lane & 7) + ((lane >> 4) & 1)*8;
    int bcolh = ((lane >> 3) & 1)*16;
    int acolh = ((lane >> 4) & 1)*16;

    for (int u = blockIdx.x; u < NUNITS; u += GRID_F){
        int tile = u >> 5, chunk = u & 31;     // NCHUNK=32
        int t0 = tile * TILE_M;
        int kb0 = chunk * KCH;

        // ---- stage zp_hi tile [128 tok x 128B] ----
#pragma unroll
        for (int i=0;i<8;i++){
            int lin = tid + 128*i;
            int r = lin >> 3, c8 = lin & 7;
            *(uint4*)(sm + OFF_ZH + SWZ128(r*128 + c8*16)) = zh4[(t0+r)*8 + c8];
        }
        // ---- cp.async e tile 0 (64 codes) + Bk into buf 0 ----
#pragma unroll
        for (int i=0;i<4;i++){
            int lin = tid + 128*i;              // 0..511
            int r = lin >> 3, c8 = lin & 7;
            cpasync16(sbase + OFF_E + SWZ128(r*128 + c8*16),
                      &eh4[(kb0 + r)*8 + c8]);
        }
        if (tid < 64) cpasync4(sbase + OFF_BK + tid*4, &g_Bk[kb0 + tid]);
        cpcommit();
        cpwait0();
        __syncthreads();

        // ---- A fragments: 2 m16 tiles per warp ----
        uint32_t afr[4][2][4];
#pragma unroll
        for (int mt=0; mt<2; mt++){
            int arow = wid*32 + mt*16 + (lane & 7) + ((lane >> 3) & 1)*8;
#pragma unroll
            for (int ks=0;ks<4;ks++){
                uint32_t addr = sbase + OFF_ZH + SWZ128(arow*128 + ks*32 + acolh);
                ldsm4(afr[ks][mt][0], afr[ks][mt][1], afr[ks][mt][2], afr[ks][mt][3], addr);
            }
        }

        int buf = 0;
        for (int it=0; it<IT_U; it++){
            if (it+1 < IT_U){
                int kbn = kb0 + (it+1)*TILE_N;
                uint32_t ebn = sbase + OFF_E + (buf^1)*8192;
#pragma unroll
                for (int i=0;i<4;i++){
                    int lin = tid + 128*i;
                    int r = lin >> 3, c8 = lin & 7;
                    cpasync16(ebn + SWZ128(r*128 + c8*16), &eh4[(kbn + r)*8 + c8]);
                }
                if (tid < 64) cpasync4(sbase + OFF_BK + (buf^1)*256 + tid*4,
                                       &g_Bk[kbn + tid]);
                cpcommit();
            }

            // ---- MMA: 32 tokens x 64 codes per warp ----
            float dacc[2][8][4];
#pragma unroll
            for (int mt=0;mt<2;mt++)
#pragma unroll
                for (int nt=0;nt<8;nt++){
                    dacc[mt][nt][0]=0.f; dacc[mt][nt][1]=0.f;
                    dacc[mt][nt][2]=0.f; dacc[mt][nt][3]=0.f;
                }
            uint32_t ebase = sbase + OFF_E + buf*8192;
#pragma unroll
            for (int ks=0;ks<4;ks++){
#pragma unroll
                for (int p=0;p<4;p++){
                    uint32_t b0,b1,b2,b3;
                    uint32_t addr = ebase + SWZ128((p*16 + brow)*128 + ks*32 + bcolh);
                    ldsm4(b0,b1,b2,b3, addr);
                    mma16816(dacc[0][2*p],   afr[ks][0], b0, b1);
                    mma16816(dacc[0][2*p+1], afr[ks][0], b2, b3);
                    mma16816(dacc[1][2*p],   afr[ks][1], b0, b1);
                    mma16816(dacc[1][2*p+1], afr[ks][1], b2, b3);
                }
            }

            // ---- epilogue: 2 groups of 32 codes x 4 token rows ----
            float gm[4][2];
#pragma unroll
            for (int g32=0; g32<2; g32++){
#pragma unroll
                for (int mt=0; mt<2; mt++){
                    float a0 = -3.402823466e38f, b0 = -3.402823466e38f;
#pragma unroll
                    for (int q=0;q<4;q++){
                        int nt = g32*4 + q;
                        float2 bk = *(const float2*)&Bk_s[buf][nt*8 + 2*tig];
                        a0 = fmaxf(a0, fmaxf(fmaf(2.f, dacc[mt][nt][0], -bk.x),
                                             fmaf(2.f, dacc[mt][nt][1], -bk.y)));
                        b0 = fmaxf(b0, fmaxf(fmaf(2.f, dacc[mt][nt][2], -bk.x),
                                             fmaf(2.f, dacc[mt][nt][3], -bk.y)));
                    }
                    a0 = fmaxf(a0, __shfl_xor_sync(0xffffffffu, a0, 1));
                    a0 = fmaxf(a0, __shfl_xor_sync(0xffffffffu, a0, 2));
                    b0 = fmaxf(b0, __shfl_xor_sync(0xffffffffu, b0, 1));
                    b0 = fmaxf(b0, __shfl_xor_sync(0xffffffffu, b0, 2));
                    gm[mt*2][g32] = a0; gm[mt*2+1][g32] = b0;
                }
            }
            if (tig == 0){
                int gidx = chunk*16 + it*2;           // global 32-code group id
#pragma unroll
                for (int tr=0; tr<4; tr++){
                    int tok = t0 + wid*32 + g + tr*8;
#pragma unroll
                    for (int g32=0; g32<2; g32++)
                        g_gmax[tok*NGRP + gidx + g32] = gm[tr][g32];
                }
            }
            if (it+1 < IT_U) cpwait0();
            __syncthreads();
            buf ^= 1;
        }
    }
}

// ---------------------------------------------------------------------------
// Kernel 4: FUSED select + rescore + finalize (unchanged from R14).
// ---------------------------------------------------------------------------
__global__ __launch_bounds__(256) void k_selres(const float* __restrict__ emb,
                                                float* __restrict__ d_out,
                                                int out_size){
    int wid = threadIdx.x >> 5, lane = threadIdx.x & 31;
    int t = blockIdx.x*8 + wid;

    const float4* gm4 = (const float4*)(g_gmax + t*NGRP);
    float4 v[4];
    float mx = -3.402823466e38f;
#pragma unroll
    for (int i=0;i<4;i++){
        v[i] = gm4[lane + 32*i];
        mx = fmaxf(mx, fmaxf(fmaxf(v[i].x, v[i].y), fmaxf(v[i].z, v[i].w)));
    }
#pragma unroll
    for (int o=16;o>0;o>>=1)
        mx = fmaxf(mx, __shfl_xor_sync(0xffffffffu, mx, o));
    float thr = mx - MARGIN;

    float A = g_A[t];
    float4 zp[16];
    const float4* zp4 = (const float4*)(g_zp + t*CD);
#pragma unroll
    for (int c4=0;c4<16;c4++) zp[c4] = zp4[c4];

    unsigned long long umin = 0xFFFFFFFFFFFFFFFFULL;
#pragma unroll
    for (int i=0;i<4;i++){
        float c[4] = {v[i].x, v[i].y, v[i].z, v[i].w};
#pragma unroll
        for (int j=0;j<4;j++){
            unsigned mask = __ballot_sync(0xffffffffu, c[j] >= thr);
            while (mask){
                int s = __ffs(mask) - 1;
                mask &= mask - 1;
                int grp = (s + 32*i)*4 + j;
                int k = grp*32 + lane;
                const float4* e4 = (const float4*)(emb + k*CD);
                float ab = 0.f;
#pragma unroll
                for (int c4=0;c4<16;c4++){
                    float4 e = e4[c4];
                    ab = fmaf(zp[c4].x, e.x, ab);
                    ab = fmaf(zp[c4].y, e.y, ab);
                    ab = fmaf(zp[c4].z, e.z, ab);
                    ab = fmaf(zp[c4].w, e.w, ab);
                }
                float sc = (A + g_Bk[k]) - 2.0f*ab;   // reference rounding
                unsigned long long uu =
                    ((unsigned long long)ford(sc) << 32) | (unsigned)k;
                umin = min(umin, uu);
            }
        }
    }
#pragma unroll
    for (int o=16;o>0;o>>=1)
        umin = min(umin, __shfl_xor_sync(0xffffffffu, umin, o));
    if (lane == 0){
        int bi = (int)(unsigned)(umin & 0xFFFFFFFFULL);
        g_idx[t] = bi;
        if (out_size > OUT_OFF_IDX + t) d_out[OUT_OFF_IDX + t] = (float)bi;
    }
}

// ---------------------------------------------------------------------------
// Kernel 5: out = emb[idx] @ Wp^T + bp + commit-loss partials.
// 128 blocks x 64 tokens (was 64 x 128 -- now fills the chip).
// ---------------------------------------------------------------------------
__global__ __launch_bounds__(256) void k_out(const float* __restrict__ emb,
                                             const float* __restrict__ Wp,
                                             const float* __restrict__ bp,
                                             float* __restrict__ d_out){
    extern __shared__ char sm[];
    char* wsm = sm;
    char* esm = sm + 256*WPROW;
    int tid = threadIdx.x;
    int t0 = blockIdx.x * 64;

    const float4* wp4 = (const float4*)Wp;
    const float4* em4 = (const float4*)emb;
#pragma unroll
    for (int i=0;i<16;i++){
        int lin = tid + 256*i;
        int d = lin >> 4, c4 = lin & 15;
        *(float4*)(wsm + d*WPROW + c4*16) = wp4[d*16 + c4];
    }
#pragma unroll
    for (int i=0;i<4;i++){
        int lin = tid + 256*i;                  // 0..1023
        int t = lin >> 4, c4 = lin & 15;
        int idx = g_idx[t0+t];
        *(float4*)(esm + t*WPROW + c4*16) = em4[idx*16 + c4];
    }
    __syncthreads();

    if (tid < 64){
        int t = tid;
        const float4* zq = (const float4*)(g_zp + (t0+t)*CD);
        float s = 0.f;
#pragma unroll
        for (int c4=0;c4<16;c4++){
            float4 e = *(const float4*)(esm + t*WPROW + c4*16);
            float4 zz = zq[c4];
            float d0 = e.x - zz.x, d1 = e.y - zz.y;
            float d2 = e.z - zz.z, d3 = e.w - zz.w;
            s = fmaf(d0,d0,s); s = fmaf(d1,d1,s);
            s = fmaf(d2,d2,s); s = fmaf(d3,d3,s);
        }
        g_part[t0+t] = s;
    }

    float w[64];
#pragma unroll
    for (int c4=0;c4<16;c4++){
        float4 ww = *(const float4*)(wsm + tid*WPROW + c4*16);
        w[4*c4+0]=ww.x; w[4*c4+1]=ww.y; w[4*c4+2]=ww.z; w[4*c4+3]=ww.w;
    }
    float bpv = bp[tid];
    for (int t=0;t<64;t++){
        float a0=0.f,a1=0.f,a2=0.f,a3=0.f;
#pragma unroll
        for (int c4=0;c4<16;c4++){
            float4 e = *(const float4*)(esm + t*WPROW + c4*16);
            a0 = fmaf(w[4*c4+0], e.x, a0);
            a1 = fmaf(w[4*c4+1], e.y, a1);
            a2 = fmaf(w[4*c4+2], e.z, a2);
            a3 = fmaf(w[4*c4+3], e.w, a3);
        }
        d_out[(t0+t)*DIMQ + tid] = (a0+a1)+(a2+a3) + bpv;
    }
}

// ---------------------------------------------------------------------------
// Kernel 6: loss = m*(1+BETA)   (single block -- deterministic)
// ---------------------------------------------------------------------------
__global__ void k_loss(float* __restrict__ d_out, int out_size){
    __shared__ float sh[256];
    int tid = threadIdx.x;
    float s = 0.f;
    for (int i=tid;i<NTOK;i+=256) s += g_part[i];
    sh[tid] = s;
    __syncthreads();
    for (int o=128;o>0;o>>=1){
        if (tid < o) sh[tid] += sh[tid+o];
        __syncthreads();
    }
    if (tid==0 && out_size > OUT_OFF_LOSS){
        float m = sh[0] / (float)(NTOK*CD);
        d_out[OUT_OFF_LOSS] = m + 0.25f*m;
    }
}

// ---------------------------------------------------------------------------
extern "C" void kernel_launch(void* const* d_in, const int* in_sizes, int n_in,
                              void* d_out, int out_size){
    const float* z   = (const float*)d_in[0];
    const float* Wq  = (const float*)d_in[1];
    const float* bq  = (const float*)d_in[2];
    const float* emb = (const float*)d_in[3];
    const float* Wp  = (const float*)d_in[4];
    const float* bp  = (const float*)d_in[5];
    float* out = (float*)d_out;
    (void)in_sizes; (void)n_in;

    static int attr_done = 0;
    if (!attr_done){
        cudaFuncSetAttribute(k_zp,     cudaFuncAttributeMaxDynamicSharedMemorySize, SMEM_ZP);
        cudaFuncSetAttribute(k_filter, cudaFuncAttributeMaxDynamicSharedMemorySize, SMEM_F);
        cudaFuncSetAttribute(k_out,    cudaFuncAttributeMaxDynamicSharedMemorySize, SMEM_KO);
        attr_done = 1;
    }

    k_zp<<<NTOK/64, 256, SMEM_ZP>>>(z, Wq, bq);          // 0
    k_B<<<NK/256, 256>>>(emb);                           // 1
    k_filter<<<GRID_F, 128, SMEM_F>>>();                 // 2
    k_selres<<<NTOK/8, 256>>>(emb, out, out_size);       // 3
    k_out<<<NTOK/64, 256, SMEM_KO>>>(emb, Wp, bp, out);  // 4
    k_loss<<<1, 256>>>(out, out_size);                   // 5
}

// round 17
// speedup vs baseline: 47.5527x; 1.0705x over previous
#include <cuda_runtime.h>
#include <cuda_bf16.h>
#include <cstdint>

#define NTOK 8192
#define DIMQ 256
#define CD   64
#define NK   16384

#define OUT_OFF_IDX  (NTOK*DIMQ)
#define OUT_OFF_LOSS (NTOK*DIMQ + NTOK)

// ---------------- filter geometry ----------------
#define TILE_M 128              // tokens per CTA (4 warps x 32)
#define TILE_N 64               // codes per staged tile
#define KCH    512              // codes per work unit
#define NCHUNK (NK/KCH)         // 32
#define NTILES (NTOK/TILE_M)    // 64
#define NUNITS (NTILES*NCHUNK)  // 2048
#define IT_U   (KCH/TILE_N)     // 8 code-tiles per unit
#define GRID_F 456              // 3 CTAs/SM x 152 SMs
#define NGRP   (NK/32)          // 512 code-groups of 32
#define MARGIN 2e-4f

// filter smem
#define OFF_ZH  0                      // 128 x 128B (SW128)  = 16384
#define OFF_E   16384                  // 2 x 64 x 128B       = 16384
#define OFF_BK  32768                  // 2 x 64 floats       = 512
#define SMEM_F  33280

// ---- k_zp smem ----
#define ZROW 1040
#define SMEM_ZP (64*ZROW*2)
// ---- k_out smem ----
#define WPROW 272
#define SMEM_KO (256*WPROW + 64*WPROW)
// ---- k_selres smem: 8 warps x 32 rows x 272B padded ----
#define SELROW 272
#define SMEM_SR (8*32*SELROW)          // 69632

#define SWZ128(o) ((o) ^ (((o) >> 3) & 0x70))

// ---------------- scratch ----------------
__device__ float g_zp[NTOK*CD];
__device__ float g_A[NTOK];
__device__ float g_Bk[NK];
__device__ __nv_bfloat16 g_zph[NTOK*CD];
__device__ __nv_bfloat16 g_eh[NK*CD];
__device__ float g_gmax[NTOK*NGRP];
__device__ int   g_idx[NTOK];
__device__ float g_part[NTOK];

__device__ __forceinline__ uint32_t smem_u32(const void* p){
    uint32_t a;
    asm("{ .reg .u64 t; cvta.to.shared.u64 t, %1; cvt.u32.u64 %0, t; }"
        : "=r"(a) : "l"(p));
    return a;
}
__device__ __forceinline__ void ldsm4(uint32_t& r0, uint32_t& r1,
                                      uint32_t& r2, uint32_t& r3, uint32_t addr){
    asm volatile("ldmatrix.sync.aligned.m8n8.x4.shared.b16 {%0,%1,%2,%3}, [%4];"
        : "=r"(r0), "=r"(r1), "=r"(r2), "=r"(r3) : "r"(addr));
}
__device__ __forceinline__ void mma16816(float* d, const uint32_t* a,
                                         uint32_t b0, uint32_t b1){
    asm volatile("mma.sync.aligned.m16n8k16.row.col.f32.bf16.bf16.f32 "
        "{%0,%1,%2,%3}, {%4,%5,%6,%7}, {%8,%9}, {%0,%1,%2,%3};"
        : "+f"(d[0]), "+f"(d[1]), "+f"(d[2]), "+f"(d[3])
        : "r"(a[0]), "r"(a[1]), "r"(a[2]), "r"(a[3]), "r"(b0), "r"(b1));
}
__device__ __forceinline__ void cpasync16(uint32_t dst, const void* src){
    asm volatile("cp.async.cg.shared.global [%0], [%1], 16;"
                 :: "r"(dst), "l"(src) : "memory");
}
__device__ __forceinline__ void cpasync4(uint32_t dst, const void* src){
    asm volatile("cp.async.ca.shared.global [%0], [%1], 4;"
                 :: "r"(dst), "l"(src) : "memory");
}
__device__ __forceinline__ void cpcommit(){
    asm volatile("cp.async.commit_group;" ::: "memory");
}
__device__ __forceinline__ void cpwait0(){
    asm volatile("cp.async.wait_group 0;" ::: "memory");
}
__device__ __forceinline__ unsigned int ford(float f){
    unsigned int b = __float_as_uint(f);
    return (b & 0x80000000u) ? ~b : (b | 0x80000000u);
}

// ---------------------------------------------------------------------------
// Kernel 1: zp = z @ Wq^T + bq (strictly-sequential ascending-d chain --
// bit-matching, DO NOT reorder) + A tree (bit-matching) + bf16-hi copy.
// ---------------------------------------------------------------------------
__global__ __launch_bounds__(256) void k_zp(const float* __restrict__ z,
                                            const float* __restrict__ Wq,
                                            const float* __restrict__ bq){
    extern __shared__ char sm[];
    char* wsm = sm;
    char* zsm = sm + 64*ZROW;
    int tid = threadIdx.x;
    int ts = tid >> 6, c = tid & 63;
    int t0 = blockIdx.x * 64;

    const float4* wq4 = (const float4*)Wq;
    const float4* z4  = (const float4*)z;
#pragma unroll
    for (int i=0;i<16;i++){
        int lin = tid + 256*i;
        int r = lin >> 6, q = lin & 63;
        *(float4*)(wsm + r*ZROW + q*16) = wq4[r*64 + q];
        *(float4*)(zsm + r*ZROW + q*16) = z4[(t0+r)*64 + q];
    }
    __syncthreads();

    float acc[16];
#pragma unroll
    for (int i=0;i<16;i++) acc[i] = 0.f;
#pragma unroll 4
    for (int k4=0;k4<64;k4++){
        float4 w = *(const float4*)(wsm + c*ZROW + k4*16);
#pragma unroll
        for (int i=0;i<16;i++){
            float4 zz = *(const float4*)(zsm + (ts*16+i)*ZROW + k4*16);
            acc[i] = fmaf(w.x, zz.x, acc[i]);
            acc[i] = fmaf(w.y, zz.y, acc[i]);
            acc[i] = fmaf(w.z, zz.z, acc[i]);
            acc[i] = fmaf(w.w, zz.w, acc[i]);
        }
    }
    float bqc = bq[c];
    float vv[16];
#pragma unroll
    for (int i=0;i<16;i++){
        float v = acc[i] + bqc;
        int gt = t0 + ts*16 + i;
        g_zp[gt*CD + c] = v;
        g_zph[gt*CD + c] = __float2bfloat16(v);
        vv[i] = v*v;
    }
    __syncthreads();
#pragma unroll
    for (int i=0;i<16;i++)
        *(float*)(zsm + (ts*16+i)*ZROW + c*4) = vv[i];
    __syncthreads();
    int l = tid & 31, w = tid >> 5;
#pragma unroll
    for (int tt=0;tt<8;tt++){
        int t = w*8 + tt;
        float s = *(float*)(zsm + t*ZROW + l*4) + *(float*)(zsm + t*ZROW + (l+32)*4);
        s += __shfl_down_sync(0xffffffffu, s, 16);
        s += __shfl_down_sync(0xffffffffu, s, 8);
        s += __shfl_down_sync(0xffffffffu, s, 4);
        s += __shfl_down_sync(0xffffffffu, s, 2);
        s += __shfl_down_sync(0xffffffffu, s, 1);
        if (l==0) g_A[t0+t] = s;
    }
}

// ---------------------------------------------------------------------------
// Kernel 2: B[k] = ||emb_k||^2 + bf16-hi copy
// ---------------------------------------------------------------------------
__global__ void k_B(const float* __restrict__ emb){
    int k = blockIdx.x*blockDim.x + threadIdx.x;
    if (k >= NK) return;
    const float4* e4 = (const float4*)(emb + k*CD);
    __nv_bfloat162* eh2 = (__nv_bfloat162*)(g_eh + k*CD);
    float s0=0.f,s1=0.f,s2=0.f,s3=0.f;
#pragma unroll
    for (int i=0;i<16;i++){
        float4 e = e4[i];
        s0=fmaf(e.x,e.x,s0); s1=fmaf(e.y,e.y,s1);
        s2=fmaf(e.z,e.z,s2); s3=fmaf(e.w,e.w,s3);
        eh2[2*i]   = __nv_bfloat162(__float2bfloat16(e.x), __float2bfloat16(e.y));
        eh2[2*i+1] = __nv_bfloat162(__float2bfloat16(e.z), __float2bfloat16(e.w));
    }
    g_Bk[k] = (s0+s1)+(s2+s3);
}

// ---------------------------------------------------------------------------
// Kernel 3: filter (UNCHANGED from R15).  Grid-strided units, 3 CTAs/SM.
// Writes per-(token, 32-code-group) max of m-hat = 2*ab - B to g_gmax.
// ---------------------------------------------------------------------------
__global__ __launch_bounds__(128, 3) void k_filter(){
    extern __shared__ char sm[];
    uint32_t sbase = smem_u32(sm);
    float (*Bk_s)[64] = (float (*)[64])(sm + OFF_BK);
    int tid = threadIdx.x;
    int wid = tid >> 5, lane = tid & 31;
    int g   = lane >> 2, tig = lane & 3;

    const uint4* zh4 = (const uint4*)g_zph;
    const uint4* eh4 = (const uint4*)g_eh;
    int brow = (lane & 7) + ((lane >> 4) & 1)*8;
    int bcolh = ((lane >> 3) & 1)*16;
    int acolh = ((lane >> 4) & 1)*16;

    for (int u = blockIdx.x; u < NUNITS; u += GRID_F){
        int tile = u >> 5, chunk = u & 31;
        int t0 = tile * TILE_M;
        int kb0 = chunk * KCH;

#pragma unroll
        for (int i=0;i<8;i++){
            int lin = tid + 128*i;
            int r = lin >> 3, c8 = lin & 7;
            *(uint4*)(sm + OFF_ZH + SWZ128(r*128 + c8*16)) = zh4[(t0+r)*8 + c8];
        }
#pragma unroll
        for (int i=0;i<4;i++){
            int lin = tid + 128*i;
            int r = lin >> 3, c8 = lin & 7;
            cpasync16(sbase + OFF_E + SWZ128(r*128 + c8*16),
                      &eh4[(kb0 + r)*8 + c8]);
        }
        if (tid < 64) cpasync4(sbase + OFF_BK + tid*4, &g_Bk[kb0 + tid]);
        cpcommit();
        cpwait0();
        __syncthreads();

        uint32_t afr[4][2][4];
#pragma unroll
        for (int mt=0; mt<2; mt++){
            int arow = wid*32 + mt*16 + (lane & 7) + ((lane >> 3) & 1)*8;
#pragma unroll
            for (int ks=0;ks<4;ks++){
                uint32_t addr = sbase + OFF_ZH + SWZ128(arow*128 + ks*32 + acolh);
                ldsm4(afr[ks][mt][0], afr[ks][mt][1], afr[ks][mt][2], afr[ks][mt][3], addr);
            }
        }

        int buf = 0;
        for (int it=0; it<IT_U; it++){
            if (it+1 < IT_U){
                int kbn = kb0 + (it+1)*TILE_N;
                uint32_t ebn = sbase + OFF_E + (buf^1)*8192;
#pragma unroll
                for (int i=0;i<4;i++){
                    int lin = tid + 128*i;
                    int r = lin >> 3, c8 = lin & 7;
                    cpasync16(ebn + SWZ128(r*128 + c8*16), &eh4[(kbn + r)*8 + c8]);
                }
                if (tid < 64) cpasync4(sbase + OFF_BK + (buf^1)*256 + tid*4,
                                       &g_Bk[kbn + tid]);
                cpcommit();
            }

            float dacc[2][8][4];
#pragma unroll
            for (int mt=0;mt<2;mt++)
#pragma unroll
                for (int nt=0;nt<8;nt++){
                    dacc[mt][nt][0]=0.f; dacc[mt][nt][1]=0.f;
                    dacc[mt][nt][2]=0.f; dacc[mt][nt][3]=0.f;
                }
            uint32_t ebase = sbase + OFF_E + buf*8192;
#pragma unroll
            for (int ks=0;ks<4;ks++){
#pragma unroll
                for (int p=0;p<4;p++){
                    uint32_t b0,b1,b2,b3;
                    uint32_t addr = ebase + SWZ128((p*16 + brow)*128 + ks*32 + bcolh);
                    ldsm4(b0,b1,b2,b3, addr);
                    mma16816(dacc[0][2*p],   afr[ks][0], b0, b1);
                    mma16816(dacc[0][2*p+1], afr[ks][0], b2, b3);
                    mma16816(dacc[1][2*p],   afr[ks][1], b0, b1);
                    mma16816(dacc[1][2*p+1], afr[ks][1], b2, b3);
                }
            }

            float gm[4][2];
#pragma unroll
            for (int g32=0; g32<2; g32++){
#pragma unroll
                for (int mt=0; mt<2; mt++){
                    float a0 = -3.402823466e38f, b0 = -3.402823466e38f;
#pragma unroll
                    for (int q=0;q<4;q++){
                        int nt = g32*4 + q;
                        float2 bk = *(const float2*)&Bk_s[buf][nt*8 + 2*tig];
                        a0 = fmaxf(a0, fmaxf(fmaf(2.f, dacc[mt][nt][0], -bk.x),
                                             fmaf(2.f, dacc[mt][nt][1], -bk.y)));
                        b0 = fmaxf(b0, fmaxf(fmaf(2.f, dacc[mt][nt][2], -bk.x),
                                             fmaf(2.f, dacc[mt][nt][3], -bk.y)));
                    }
                    a0 = fmaxf(a0, __shfl_xor_sync(0xffffffffu, a0, 1));
                    a0 = fmaxf(a0, __shfl_xor_sync(0xffffffffu, a0, 2));
                    b0 = fmaxf(b0, __shfl_xor_sync(0xffffffffu, b0, 1));
                    b0 = fmaxf(b0, __shfl_xor_sync(0xffffffffu, b0, 2));
                    gm[mt*2][g32] = a0; gm[mt*2+1][g32] = b0;
                }
            }
            if (tig == 0){
                int gidx = chunk*16 + it*2;
#pragma unroll
                for (int tr=0; tr<4; tr++){
                    int tok = t0 + wid*32 + g + tr*8;
#pragma unroll
                    for (int g32=0; g32<2; g32++)
                        g_gmax[tok*NGRP + gidx + g32] = gm[tr][g32];
                }
            }
            if (it+1 < IT_U) cpwait0();
            __syncthreads();
            buf ^= 1;
        }
    }
}

// ---------------------------------------------------------------------------
// Kernel 4: FUSED select + rescore + finalize.  Warp per token.
// NEW: qualifying group rows are staged through padded smem with a
// COALESCED warp copy (64 wf vs 512 scattered), then each lane rescoring
// its code reads its own smem row conflict-free.  Pure copy -> identical
// bit values -> identical scores and lexicographic (s,k) min.
// ---------------------------------------------------------------------------
__global__ __launch_bounds__(256) void k_selres(const float* __restrict__ emb,
                                                float* __restrict__ d_out,
                                                int out_size){
    extern __shared__ char sm[];
    int wid = threadIdx.x >> 5, lane = threadIdx.x & 31;
    char* wbuf = sm + wid*(32*SELROW);
    int t = blockIdx.x*8 + wid;

    const float4* gm4 = (const float4*)(g_gmax + t*NGRP);
    float4 v[4];
    float mx = -3.402823466e38f;
#pragma unroll
    for (int i=0;i<4;i++){
        v[i] = gm4[lane + 32*i];
        mx = fmaxf(mx, fmaxf(fmaxf(v[i].x, v[i].y), fmaxf(v[i].z, v[i].w)));
    }
#pragma unroll
    for (int o=16;o>0;o>>=1)
        mx = fmaxf(mx, __shfl_xor_sync(0xffffffffu, mx, o));
    float thr = mx - MARGIN;

    float A = g_A[t];
    float4 zp[16];
    const float4* zp4 = (const float4*)(g_zp + t*CD);
#pragma unroll
    for (int c4=0;c4<16;c4++) zp[c4] = zp4[c4];

    unsigned long long umin = 0xFFFFFFFFFFFFFFFFULL;
#pragma unroll
    for (int i=0;i<4;i++){
        float c[4] = {v[i].x, v[i].y, v[i].z, v[i].w};
#pragma unroll
        for (int j=0;j<4;j++){
            unsigned mask = __ballot_sync(0xffffffffu, c[j] >= thr);
            while (mask){
                int s = __ffs(mask) - 1;
                mask &= mask - 1;
                int grp = (s + 32*i)*4 + j;
                // ---- coalesced stage of the 32x64f group block ----
                const float4* src = (const float4*)(emb + grp*32*CD); // 512 f4
#pragma unroll
                for (int q=0;q<16;q++){
                    int f = q*32 + lane;
                    int row = f >> 4, c4 = f & 15;
                    *(float4*)(wbuf + row*SELROW + c4*16) = src[f];
                }
                __syncwarp();
                // ---- exact rescore: lane's own smem row, sequential chain ----
                int k = grp*32 + lane;
                float ab = 0.f;
#pragma unroll
                for (int c4=0;c4<16;c4++){
                    float4 e = *(const float4*)(wbuf + lane*SELROW + c4*16);
                    ab = fmaf(zp[c4].x, e.x, ab);
                    ab = fmaf(zp[c4].y, e.y, ab);
                    ab = fmaf(zp[c4].z, e.z, ab);
                    ab = fmaf(zp[c4].w, e.w, ab);
                }
                float sc = (A + g_Bk[k]) - 2.0f*ab;   // reference rounding
                unsigned long long uu =
                    ((unsigned long long)ford(sc) << 32) | (unsigned)k;
                umin = min(umin, uu);
                __syncwarp();          // staging of next group can't overlap
            }
        }
    }
#pragma unroll
    for (int o=16;o>0;o>>=1)
        umin = min(umin, __shfl_xor_sync(0xffffffffu, umin, o));
    if (lane == 0){
        int bi = (int)(unsigned)(umin & 0xFFFFFFFFULL);
        g_idx[t] = bi;
        if (out_size > OUT_OFF_IDX + t) d_out[OUT_OFF_IDX + t] = (float)bi;
    }
}

// ---------------------------------------------------------------------------
// Kernel 5: out = emb[idx] @ Wp^T + bp + commit-loss partials.
// 128 blocks x 64 tokens.
// ---------------------------------------------------------------------------
__global__ __launch_bounds__(256) void k_out(const float* __restrict__ emb,
                                             const float* __restrict__ Wp,
                                             const float* __restrict__ bp,
                                             float* __restrict__ d_out){
    extern __shared__ char sm[];
    char* wsm = sm;
    char* esm = sm + 256*WPROW;
    int tid = threadIdx.x;
    int t0 = blockIdx.x * 64;

    const float4* wp4 = (const float4*)Wp;
    const float4* em4 = (const float4*)emb;
#pragma unroll
    for (int i=0;i<16;i++){
        int lin = tid + 256*i;
        int d = lin >> 4, c4 = lin & 15;
        *(float4*)(wsm + d*WPROW + c4*16) = wp4[d*16 + c4];
    }
#pragma unroll
    for (int i=0;i<4;i++){
        int lin = tid + 256*i;
        int t = lin >> 4, c4 = lin & 15;
        int idx = g_idx[t0+t];
        *(float4*)(esm + t*WPROW + c4*16) = em4[idx*16 + c4];
    }
    __syncthreads();

    if (tid < 64){
        int t = tid;
        const float4* zq = (const float4*)(g_zp + (t0+t)*CD);
        float s = 0.f;
#pragma unroll
        for (int c4=0;c4<16;c4++){
            float4 e = *(const float4*)(esm + t*WPROW + c4*16);
            float4 zz = zq[c4];
            float d0 = e.x - zz.x, d1 = e.y - zz.y;
            float d2 = e.z - zz.z, d3 = e.w - zz.w;
            s = fmaf(d0,d0,s); s = fmaf(d1,d1,s);
            s = fmaf(d2,d2,s); s = fmaf(d3,d3,s);
        }
        g_part[t0+t] = s;
    }

    float w[64];
#pragma unroll
    for (int c4=0;c4<16;c4++){
        float4 ww = *(const float4*)(wsm + tid*WPROW + c4*16);
        w[4*c4+0]=ww.x; w[4*c4+1]=ww.y; w[4*c4+2]=ww.z; w[4*c4+3]=ww.w;
    }
    float bpv = bp[tid];
    for (int t=0;t<64;t++){
        float a0=0.f,a1=0.f,a2=0.f,a3=0.f;
#pragma unroll
        for (int c4=0;c4<16;c4++){
            float4 e = *(const float4*)(esm + t*WPROW + c4*16);
            a0 = fmaf(w[4*c4+0], e.x, a0);
            a1 = fmaf(w[4*c4+1], e.y, a1);
            a2 = fmaf(w[4*c4+2], e.z, a2);
            a3 = fmaf(w[4*c4+3], e.w, a3);
        }
        d_out[(t0+t)*DIMQ + tid] = (a0+a1)+(a2+a3) + bpv;
    }
}

// ---------------------------------------------------------------------------
// Kernel 6: loss = m*(1+BETA)   (single block -- deterministic)
// ---------------------------------------------------------------------------
__global__ void k_loss(float* __restrict__ d_out, int out_size){
    __shared__ float sh[256];
    int tid = threadIdx.x;
    float s = 0.f;
    for (int i=tid;i<NTOK;i+=256) s += g_part[i];
    sh[tid] = s;
    __syncthreads();
    for (int o=128;o>0;o>>=1){
        if (tid < o) sh[tid] += sh[tid+o];
        __syncthreads();
    }
    if (tid==0 && out_size > OUT_OFF_LOSS){
        float m = sh[0] / (float)(NTOK*CD);
        d_out[OUT_OFF_LOSS] = m + 0.25f*m;
    }
}

// ---------------------------------------------------------------------------
extern "C" void kernel_launch(void* const* d_in, const int* in_sizes, int n_in,
                              void* d_out, int out_size){
    const float* z   = (const float*)d_in[0];
    const float* Wq  = (const float*)d_in[1];
    const float* bq  = (const float*)d_in[2];
    const float* emb = (const float*)d_in[3];
    const float* Wp  = (const float*)d_in[4];
    const float* bp  = (const float*)d_in[5];
    float* out = (float*)d_out;
    (void)in_sizes; (void)n_in;

    static int attr_done = 0;
    if (!attr_done){
        cudaFuncSetAttribute(k_zp,     cudaFuncAttributeMaxDynamicSharedMemorySize, SMEM_ZP);
        cudaFuncSetAttribute(k_filter, cudaFuncAttributeMaxDynamicSharedMemorySize, SMEM_F);
        cudaFuncSetAttribute(k_selres, cudaFuncAttributeMaxDynamicSharedMemorySize, SMEM_SR);
        cudaFuncSetAttribute(k_out,    cudaFuncAttributeMaxDynamicSharedMemorySize, SMEM_KO);
        attr_done = 1;
    }

    k_zp<<<NTOK/64, 256, SMEM_ZP>>>(z, Wq, bq);          // 0
    k_B<<<NK/256, 256>>>(emb);                           // 1
    k_filter<<<GRID_F, 128, SMEM_F>>>();                 // 2
    k_selres<<<NTOK/8, 256, SMEM_SR>>>(emb, out, out_size); // 3 (profiled)
    k_out<<<NTOK/64, 256, SMEM_KO>>>(emb, Wp, bp, out);  // 4
    k_loss<<<1, 256>>>(out, out_size);                   // 5
}